// round 1
// baseline (speedup 1.0000x reference)
#include <cuda_runtime.h>

// ---------------------------------------------------------------------------
// Persistent-grid LSTM: 128 resident blocks (16 batch-groups x 8 hidden-chunks),
// weights SMEM-resident for the whole sequence, custom grid barrier per step.
// ---------------------------------------------------------------------------

namespace {
constexpr int Bb   = 256;
constexpr int Tt   = 200;
constexpr int Fd   = 16;
constexpr int Hh   = 256;
constexpr int KTOT = 274;        // 18 (inp) + 256 (h)
constexpr int NBLK = 128;        // 16 batch groups * 8 hidden chunks
constexpr int BG   = 16;         // batch rows per group
constexpr int RB   = 128;        // gate rows per block (4 gates * 32 hidden)
constexpr int HCn  = 32;         // hidden per chunk
constexpr int THREADS = 256;

// shared memory layout (bytes)
constexpr int OFF_WS   = 0;                      // 274*128 f32      = 140288
constexpr int OFF_HDUP = 140288;                 // 274*16  float2   =  35072
constexpr int OFF_W1   = 175360;                 // 8*256   f32      =   8192
constexpr int OFF_GBUF = 183552;                 // 16*128  f32      =   8192
constexpr int OFF_CARR = 191744;                 // 512     f32      =   2048
constexpr int OFF_HB   = 193792;                 // 16*256  f32      =  16384
constexpr int OFF_BSL  = 210176;                 // 64      float2   =    512
constexpr int OFF_ZLOC = 210688;                 // 16 f32 (pad 64)
constexpr int OFF_W2   = 210752;                 // 8 f32  (pad 32)
constexpr int OFF_B1   = 210784;                 // 8 f32  (pad 32)
constexpr int OFF_B2   = 210816;                 // 1 f32
constexpr int SMEM_BYTES = 210944;

constexpr int OUT_H = Bb * Tt;                   // 51200
constexpr int OUT_C = OUT_H + Bb * Hh;           // 116736
}

__device__ unsigned g_arrive;      // zero-init; returns to 0 every barrier
__device__ unsigned g_epoch;      // monotone (wraps), fine across graph replays
__device__ float    g_hbuf[2][Bb][Hh];
__device__ float    g_part[NBLK][BG];

typedef unsigned long long u64;

__device__ __forceinline__ u64 fma2(u64 a, u64 b, u64 c) {
    u64 d;
    asm("fma.rn.f32x2 %0, %1, %2, %3;" : "=l"(d) : "l"(a), "l"(b), "l"(c));
    return d;
}

__device__ __forceinline__ float sigf(float x) {
    return __fdividef(1.0f, 1.0f + __expf(-x));
}
__device__ __forceinline__ float tanh_(float x) {
    return 1.0f - __fdividef(2.0f, __expf(2.0f * x) + 1.0f);
}

// All 128 blocks are resident (1 block/SM at 206KB smem), so spinning is safe.
__device__ __forceinline__ void grid_sync() {
    __syncthreads();
    if (threadIdx.x == 0) {
        unsigned e = *(volatile unsigned*)&g_epoch;   // read BEFORE arriving
        __threadfence();                              // release my block's writes
        if (atomicAdd(&g_arrive, 1u) == NBLK - 1) {
            g_arrive = 0u;
            __threadfence();
            atomicAdd(&g_epoch, 1u);
        } else {
            while (*(volatile unsigned*)&g_epoch == e) { __nanosleep(32); }
        }
        __threadfence();                              // acquire
    }
    __syncthreads();
}

__global__ void __launch_bounds__(THREADS, 1)
lstm_persistent_kernel(const float* __restrict__ zin,  const float* __restrict__ xin,
                       const float* __restrict__ h0,   const float* __restrict__ Wih,
                       const float* __restrict__ Whh,  const float* __restrict__ bias,
                       const float* __restrict__ W1,   const float* __restrict__ b1,
                       const float* __restrict__ W2,   const float* __restrict__ b2,
                       float* __restrict__ out)
{
    extern __shared__ char smem[];
    float*  Ws   = (float*) (smem + OFF_WS);    // k-major: Ws[k*128 + r]
    float2* hdup = (float2*)(smem + OFF_HDUP);  // (v,v) pairs: hdup[k*16 + b]
    float*  W1s  = (float*) (smem + OFF_W1);    // W1s[f*256 + k], f = local 0..7
    float*  gbuf = (float*) (smem + OFF_GBUF);  // gbuf[b*128 + r]
    float*  carr = (float*) (smem + OFF_CARR);  // c state: [b*32 + j]
    float*  hb   = (float*) (smem + OFF_HB);    // phase-B h tile [b*256 + k]
    float2* bsl  = (float2*)(smem + OFF_BSL);   // bias row-pairs
    float*  zloc = (float*) (smem + OFF_ZLOC);  // z_{t-1} per batch row
    float*  W2s  = (float*) (smem + OFF_W2);
    float*  b1s  = (float*) (smem + OFF_B1);
    float*  b2s  = (float*) (smem + OFF_B2);

    const int tid = threadIdx.x;
    const int bg  = blockIdx.x >> 3;   // batch group 0..15
    const int hc  = blockIdx.x & 7;    // hidden chunk 0..7
    const int k0  = hc * HCn;

    // ---- prologue: load weight slices once ------------------------------
    for (int idx = tid; idx < KTOT * RB; idx += THREADS) {
        int k = idx >> 7, r = idx & 127;
        int grow = ((r >> 5) << 8) + k0 + (r & 31);       // gate*256 + k0 + j
        Ws[idx] = (k < 18) ? Wih[grow * 18 + k] : Whh[(grow << 8) + (k - 18)];
    }
    for (int idx = tid; idx < 8 * Hh; idx += THREADS)
        W1s[idx] = W1[(hc * 8 + (idx >> 8)) * Hh + (idx & 255)];
    if (tid < 64) {
        int r0 = 2 * tid, r1 = r0 + 1;
        float v0 = bias[((r0 >> 5) << 8) + k0 + (r0 & 31)];
        float v1 = bias[((r1 >> 5) << 8) + k0 + (r1 & 31)];
        bsl[tid] = make_float2(v0, v1);
    }
    if (tid < 8) { W2s[tid] = W2[hc * 8 + tid]; b1s[tid] = b1[hc * 8 + tid]; }
    if (tid == 0) *b2s = b2[0];
    for (int idx = tid; idx < BG * HCn; idx += THREADS) carr[idx] = 0.f;
    if (tid < BG) zloc[tid] = 0.f;
    __syncthreads();

    // ---- time loop -------------------------------------------------------
    for (int t = 0; t < Tt; ++t) {
        // finalize z_{t-1} from FF partials (redundant per block, fixed order)
        if (t > 0) {
            if (tid < BG) {
                float s = *b2s;
                #pragma unroll
                for (int c = 0; c < 8; ++c) s += g_part[(bg << 3) + c][tid];
                float zn = zloc[tid] + fmaxf(s, 0.f);
                zloc[tid] = zn;
                if (hc == 0) out[(bg * BG + tid) * Tt + (t - 1)] = zn;
            }
            __syncthreads();
        }

        // fill hdup[k][b] = (v,v): inp = [z_t, x_t(16), z_prev] ++ h_{t-1}
        {
            const int fb = tid >> 4, fl = tid & 15;
            const int bglob = bg * BG + fb;
            const float* hsrc = (t == 0) ? (h0 + bglob * Hh)
                                         : &g_hbuf[(t - 1) & 1][bglob][0];
            const float zt = zin[bglob * Tt + t];
            const float zp = zloc[fb];
            const float* xr = xin + (bglob * Tt + t) * Fd;
            for (int k = fl; k < KTOT; k += 16) {
                float v;
                if (k >= 18)      v = hsrc[k - 18];
                else if (k == 0)  v = zt;
                else if (k <= 16) v = xr[k - 1];
                else              v = zp;
                hdup[(k << 4) + fb] = make_float2(v, v);
            }
        }
        __syncthreads();

        // phase A: g[b, r] = bias + sum_k inp/h * W   (f32x2, rows packed)
        {
            const int bq = tid >> 6;          // batch quad 0..3
            const int rp = tid & 63;          // row pair 0..63
            const u64* __restrict__ wp = ((const u64*)Ws) + rp;
            const ulonglong2* __restrict__ hp = ((const ulonglong2*)hdup) + (bq << 1);
            union { float2 f; u64 u; } cv; cv.f = bsl[rp];
            u64 a0 = cv.u, a1 = cv.u, a2 = cv.u, a3 = cv.u;
            #pragma unroll 2
            for (int k = 0; k < KTOT; ++k) {
                u64 w = wp[k << 6];
                ulonglong2 h01 = hp[(k << 3)];
                ulonglong2 h23 = hp[(k << 3) + 1];
                a0 = fma2(w, h01.x, a0);
                a1 = fma2(w, h01.y, a1);
                a2 = fma2(w, h23.x, a2);
                a3 = fma2(w, h23.y, a3);
            }
            float2* g2 = (float2*)gbuf;
            int bb = bq << 2;
            union { u64 u; float2 f; } o0, o1, o2, o3;
            o0.u = a0; o1.u = a1; o2.u = a2; o3.u = a3;
            g2[(bb + 0) * 64 + rp] = o0.f;
            g2[(bb + 1) * 64 + rp] = o1.f;
            g2[(bb + 2) * 64 + rp] = o2.f;
            g2[(bb + 3) * 64 + rp] = o3.f;
        }
        __syncthreads();

        // gate nonlinearities + state update; publish h chunk
        {
            const int wbuf = t & 1;
            for (int idx = tid; idx < BG * HCn; idx += THREADS) {
                int b = idx >> 5, j = idx & 31;
                float gi = gbuf[(b << 7) + j];
                float gf = gbuf[(b << 7) + 32 + j];
                float gg = gbuf[(b << 7) + 64 + j];
                float go = gbuf[(b << 7) + 96 + j];
                float c = carr[idx];
                c = sigf(gf) * c + sigf(gi) * tanh_(gg);
                float h = sigf(go) * tanh_(c);
                carr[idx] = c;
                int bglob = bg * BG + b;
                g_hbuf[wbuf][bglob][k0 + j] = h;
                if (t == Tt - 1) {
                    out[OUT_H + bglob * Hh + k0 + j] = h;
                    out[OUT_C + bglob * Hh + k0 + j] = c;
                }
            }
        }
        grid_sync();

        // phase B: FF head, FWD rows [hc*8, hc*8+8) for this batch group
        {
            const int wbuf = t & 1;
            for (int idx = tid; idx < BG * Hh; idx += THREADS)
                hb[idx] = g_hbuf[wbuf][bg * BG + (idx >> 8)][idx & 255];
            __syncthreads();
            if (tid < 128) {
                int b = tid >> 3, f = tid & 7;
                const float4* hv = (const float4*)(hb + (b << 8));
                const float4* wv = (const float4*)(W1s + (f << 8));
                float s = b1s[f];
                #pragma unroll 16
                for (int q = 0; q < Hh / 4; ++q) {
                    float4 hq = hv[q], wq = wv[q];
                    s = fmaf(hq.x, wq.x, s); s = fmaf(hq.y, wq.y, s);
                    s = fmaf(hq.z, wq.z, s); s = fmaf(hq.w, wq.w, s);
                }
                float r = fmaxf(s, 0.f) * W2s[f];
                r += __shfl_xor_sync(0xffffffffu, r, 1);
                r += __shfl_xor_sync(0xffffffffu, r, 2);
                r += __shfl_xor_sync(0xffffffffu, r, 4);
                if (f == 0) g_part[blockIdx.x][b] = r;
            }
        }
        grid_sync();
    }

    // epilogue: finalize z_{T-1}
    if (hc == 0 && tid < BG) {
        float s = *b2s;
        #pragma unroll
        for (int c = 0; c < 8; ++c) s += g_part[(bg << 3) + c][tid];
        float zn = zloc[tid] + fmaxf(s, 0.f);
        out[(bg * BG + tid) * Tt + (Tt - 1)] = zn;
    }
}

extern "C" void kernel_launch(void* const* d_in, const int* in_sizes, int n_in,
                              void* d_out, int out_size) {
    const float* z   = (const float*)d_in[0];
    const float* x   = (const float*)d_in[1];
    const float* h0  = (const float*)d_in[2];
    const float* Wih = (const float*)d_in[3];
    const float* Whh = (const float*)d_in[4];
    const float* b   = (const float*)d_in[5];
    const float* W1  = (const float*)d_in[6];
    const float* b1  = (const float*)d_in[7];
    const float* W2  = (const float*)d_in[8];
    const float* b2  = (const float*)d_in[9];
    float* out = (float*)d_out;

    cudaFuncSetAttribute(lstm_persistent_kernel,
                         cudaFuncAttributeMaxDynamicSharedMemorySize, SMEM_BYTES);
    lstm_persistent_kernel<<<NBLK, THREADS, SMEM_BYTES>>>(
        z, x, h0, Wih, Whh, b, W1, b1, W2, b2, out);
}

// round 2
// speedup vs baseline: 1.1322x; 1.1322x over previous
#include <cuda_runtime.h>

// ---------------------------------------------------------------------------
// Persistent-grid LSTM: 128 resident blocks (16 batch-groups x 8 hidden-chunks),
// weights SMEM-resident, crossbar-optimal phase-A tiling, acq/rel grid barrier.
// ---------------------------------------------------------------------------

namespace {
constexpr int Bb   = 256;
constexpr int Tt   = 200;
constexpr int Fd   = 16;
constexpr int Hh   = 256;
constexpr int KTOT = 274;        // 18 (inp) + 256 (h)
constexpr int NBLK = 128;        // 16 batch groups * 8 hidden chunks
constexpr int BG   = 16;         // batch rows per group
constexpr int RB   = 128;        // gate rows per block (4 gates * 32 hidden)
constexpr int HCn  = 32;         // hidden per chunk
constexpr int THREADS = 256;
constexpr int HST  = 18;         // hdup row stride in u64 (16 batches + 2 pad)

// shared memory layout (bytes), all 16B aligned
constexpr int OFF_WS   = 0;                 // 274*128 f32          = 140288
constexpr int OFF_HDUP = 140288;            // 274*18  u64          =  39456
constexpr int OFF_W1   = 179744;            // 8*256   f32          =   8192
constexpr int OFF_GBUF = 187936;            // 16*128  f32          =   8192
constexpr int OFF_CARR = 196128;            // 512     f32          =   2048
constexpr int OFF_HB   = 198176;            // 16*256  f32          =  16384
constexpr int OFF_BSL  = 214560;            // 64      float2       =    512
constexpr int OFF_ZLOC = 215072;            // 16 f32 (pad 64)
constexpr int OFF_W2   = 215136;            // 8 f32 (pad 32)
constexpr int OFF_B1   = 215168;            // 8 f32 (pad 32)
constexpr int OFF_B2   = 215200;            // 1 f32 (pad 32)
constexpr int SMEM_BYTES = 215232;

constexpr int OUT_H = Bb * Tt;              // 51200
constexpr int OUT_C = OUT_H + Bb * Hh;      // 116736
}

__device__ unsigned g_arrive;      // self-resetting
__device__ unsigned g_epoch;       // monotone (wraps); consistent across replays
__device__ float    g_hbuf[2][Bb][Hh];
__device__ float    g_part[NBLK][BG];

typedef unsigned long long u64;

__device__ __forceinline__ u64 fma2(u64 a, u64 b, u64 c) {
    u64 d;
    asm("fma.rn.f32x2 %0, %1, %2, %3;" : "=l"(d) : "l"(a), "l"(b), "l"(c));
    return d;
}

__device__ __forceinline__ float sigf(float x) {
    return __fdividef(1.0f, 1.0f + __expf(-x));
}
__device__ __forceinline__ float tanh_(float x) {
    return 1.0f - __fdividef(2.0f, __expf(2.0f * x) + 1.0f);
}

// All 128 blocks are resident (1 block/SM), so spinning is deadlock-free.
__device__ __forceinline__ void grid_sync() {
    __syncthreads();
    if (threadIdx.x == 0) {
        unsigned e;
        asm volatile("ld.acquire.gpu.global.u32 %0, [%1];"
                     : "=r"(e) : "l"(&g_epoch) : "memory");
        unsigned old;
        asm volatile("atom.acq_rel.gpu.global.add.u32 %0, [%1], %2;"
                     : "=r"(old) : "l"(&g_arrive), "r"(1u) : "memory");
        if (old == NBLK - 1) {
            asm volatile("st.relaxed.gpu.global.u32 [%0], %1;"
                         :: "l"(&g_arrive), "r"(0u) : "memory");
            asm volatile("red.release.gpu.global.add.u32 [%0], %1;"
                         :: "l"(&g_epoch), "r"(1u) : "memory");
        } else {
            unsigned cur;
            do {
                asm volatile("ld.acquire.gpu.global.u32 %0, [%1];"
                             : "=r"(cur) : "l"(&g_epoch) : "memory");
            } while (cur == e);
        }
    }
    __syncthreads();
}

__global__ void __launch_bounds__(THREADS, 1)
lstm_persistent_kernel(const float* __restrict__ zin,  const float* __restrict__ xin,
                       const float* __restrict__ h0,   const float* __restrict__ Wih,
                       const float* __restrict__ Whh,  const float* __restrict__ bias,
                       const float* __restrict__ W1,   const float* __restrict__ b1,
                       const float* __restrict__ W2,   const float* __restrict__ b2,
                       float* __restrict__ out)
{
    extern __shared__ char smem[];
    float*  Ws    = (float*) (smem + OFF_WS);    // k-major: Ws[k*128 + r]
    u64*    hdup  = (u64*)   (smem + OFF_HDUP);  // (v,v) dup: hdup[k*HST + b]
    float*  W1s   = (float*) (smem + OFF_W1);    // W1s[f*256 + k]
    float*  gbuf  = (float*) (smem + OFF_GBUF);  // gbuf[b*128 + r]
    float*  carr  = (float*) (smem + OFF_CARR);  // c state [b*32 + j]
    float*  hb    = (float*) (smem + OFF_HB);    // phase-B h tile [b*256 + k]
    float2* bsl   = (float2*)(smem + OFF_BSL);   // bias row-pairs
    float*  zloc  = (float*) (smem + OFF_ZLOC);
    float*  W2s   = (float*) (smem + OFF_W2);
    float*  b1s   = (float*) (smem + OFF_B1);
    float*  b2s   = (float*) (smem + OFF_B2);

    const int tid = threadIdx.x;
    const int bg  = blockIdx.x >> 3;   // batch group 0..15
    const int hc  = blockIdx.x & 7;    // hidden chunk 0..7
    const int k0  = hc * HCn;

    // ---- prologue: load weight slices once ------------------------------
    for (int idx = tid; idx < KTOT * RB; idx += THREADS) {
        int k = idx >> 7, r = idx & 127;
        int grow = ((r >> 5) << 8) + k0 + (r & 31);       // gate*256 + k0 + j
        Ws[idx] = (k < 18) ? Wih[grow * 18 + k] : Whh[(grow << 8) + (k - 18)];
    }
    for (int idx = tid; idx < 8 * Hh; idx += THREADS)
        W1s[idx] = W1[(hc * 8 + (idx >> 8)) * Hh + (idx & 255)];
    if (tid < 64) {
        int r0 = 2 * tid, r1 = r0 + 1;
        float v0 = bias[((r0 >> 5) << 8) + k0 + (r0 & 31)];
        float v1 = bias[((r1 >> 5) << 8) + k0 + (r1 & 31)];
        bsl[tid] = make_float2(v0, v1);
    }
    if (tid < 8) { W2s[tid] = W2[hc * 8 + tid]; b1s[tid] = b1[hc * 8 + tid]; }
    if (tid == 0) *b2s = b2[0];
    for (int idx = tid; idx < BG * HCn; idx += THREADS) carr[idx] = 0.f;
    if (tid < BG) zloc[tid] = 0.f;
    __syncthreads();

    // phase-A lane geometry: warp = 32 rows x 8 batches; lane = 4 rows x 2 batches
    const int wrp = tid >> 5, lan = tid & 31;
    const int rg  = (wrp & 3) << 5;            // row group base: 0,32,64,96
    const int bgl = (wrp >> 2) << 3;           // batch group base: 0 or 8
    const int rq  = (lan & 7) << 2;            // row quad offset 0..28
    const int bp  = (lan >> 3) << 1;           // batch pair offset 0,2,4,6
    const int r0  = rg + rq;                   // first of 4 rows
    const int b0  = bgl + bp;                  // first of 2 batches
    const char* wbB = (const char*)(Ws + r0);                 // + k*512
    const char* hbB = (const char*)(hdup + b0);               // + k*144

    // ---- time loop -------------------------------------------------------
    for (int t = 0; t < Tt; ++t) {
        // finalize z_{t-1} from FF partials (redundant per block, fixed order)
        if (t > 0) {
            if (tid < BG) {
                float s = *b2s;
                #pragma unroll
                for (int c = 0; c < 8; ++c) s += g_part[(bg << 3) + c][tid];
                float zn = zloc[tid] + fmaxf(s, 0.f);
                zloc[tid] = zn;
                if (hc == 0) out[(bg * BG + tid) * Tt + (t - 1)] = zn;
            }
            __syncthreads();
        }

        // fill hdup[k][b] = (v,v): inp = [z_t, x_t(16), z_prev] ++ h_{t-1}
        {
            const int fb = tid >> 4, fl = tid & 15;
            const int bglob = bg * BG + fb;
            const float* hsrc = (t == 0) ? (h0 + bglob * Hh)
                                         : &g_hbuf[(t - 1) & 1][bglob][0];
            const float zt = zin[bglob * Tt + t];
            const float zp = zloc[fb];
            const float* xr = xin + (bglob * Tt + t) * Fd;
            for (int k = fl; k < KTOT; k += 16) {
                float v;
                if (k >= 18)      v = hsrc[k - 18];
                else if (k == 0)  v = zt;
                else if (k <= 16) v = xr[k - 1];
                else              v = zp;
                union { float2 f; u64 u; } d;
                d.f = make_float2(v, v);
                hdup[k * HST + fb] = d.u;
            }
        }
        __syncthreads();

        // phase A: g[b, r] = bias + sum_k inp/h * W
        // lane: w row-quad (LDS.128, 1 phase/warp) x h batch-pair (LDS.128, 1 phase/warp)
        {
            u64 a00, a01, a10, a11;
            {
                union { float2 f; u64 u; } c0, c1;
                c0.f = bsl[r0 >> 1];
                c1.f = bsl[(r0 >> 1) + 1];
                a00 = c0.u; a01 = c0.u; a10 = c1.u; a11 = c1.u;
            }
            #pragma unroll 4
            for (int k = 0; k < KTOT; ++k) {
                ulonglong2 wv = *(const ulonglong2*)(wbB + (size_t)k * 512);
                ulonglong2 hv = *(const ulonglong2*)(hbB + (size_t)k * (HST * 8));
                a00 = fma2(wv.x, hv.x, a00);
                a01 = fma2(wv.x, hv.y, a01);
                a10 = fma2(wv.y, hv.x, a10);
                a11 = fma2(wv.y, hv.y, a11);
            }
            float2* g2 = (float2*)gbuf;
            const int rp0 = r0 >> 1;
            union { u64 u; float2 f; } o;
            o.u = a00; g2[(b0    ) * 64 + rp0    ] = o.f;
            o.u = a10; g2[(b0    ) * 64 + rp0 + 1] = o.f;
            o.u = a01; g2[(b0 + 1) * 64 + rp0    ] = o.f;
            o.u = a11; g2[(b0 + 1) * 64 + rp0 + 1] = o.f;
        }
        __syncthreads();

        // gate nonlinearities + state update; publish h chunk
        {
            const int wbuf = t & 1;
            for (int idx = tid; idx < BG * HCn; idx += THREADS) {
                int b = idx >> 5, j = idx & 31;
                float gi = gbuf[(b << 7) + j];
                float gf = gbuf[(b << 7) + 32 + j];
                float gg = gbuf[(b << 7) + 64 + j];
                float go = gbuf[(b << 7) + 96 + j];
                float c = carr[idx];
                c = sigf(gf) * c + sigf(gi) * tanh_(gg);
                float h = sigf(go) * tanh_(c);
                carr[idx] = c;
                int bglob = bg * BG + b;
                g_hbuf[wbuf][bglob][k0 + j] = h;
                if (t == Tt - 1) {
                    out[OUT_H + bglob * Hh + k0 + j] = h;
                    out[OUT_C + bglob * Hh + k0 + j] = c;
                }
            }
        }
        grid_sync();

        // phase B: FF head, FWD rows [hc*8, hc*8+8) for this batch group
        {
            const int wbuf = t & 1;
            const float4* src = (const float4*)&g_hbuf[wbuf][bg * BG][0];
            float4* dst = (float4*)hb;
            for (int idx = tid; idx < BG * Hh / 4; idx += THREADS)
                dst[idx] = src[idx];
            __syncthreads();
            if (tid < 128) {
                int b = tid >> 3, f = tid & 7;
                const float4* hv = (const float4*)(hb + (b << 8));
                const float4* wv = (const float4*)(W1s + (f << 8));
                float s = b1s[f];
                #pragma unroll 16
                for (int q = 0; q < Hh / 4; ++q) {
                    float4 hq = hv[q], wq = wv[q];
                    s = fmaf(hq.x, wq.x, s); s = fmaf(hq.y, wq.y, s);
                    s = fmaf(hq.z, wq.z, s); s = fmaf(hq.w, wq.w, s);
                }
                float r = fmaxf(s, 0.f) * W2s[f];
                r += __shfl_xor_sync(0xffffffffu, r, 1);
                r += __shfl_xor_sync(0xffffffffu, r, 2);
                r += __shfl_xor_sync(0xffffffffu, r, 4);
                if (f == 0) g_part[blockIdx.x][b] = r;
            }
        }
        grid_sync();
    }

    // epilogue: finalize z_{T-1}
    if (hc == 0 && tid < BG) {
        float s = *b2s;
        #pragma unroll
        for (int c = 0; c < 8; ++c) s += g_part[(bg << 3) + c][tid];
        float zn = zloc[tid] + fmaxf(s, 0.f);
        out[(bg * BG + tid) * Tt + (Tt - 1)] = zn;
    }
}

extern "C" void kernel_launch(void* const* d_in, const int* in_sizes, int n_in,
                              void* d_out, int out_size) {
    const float* z   = (const float*)d_in[0];
    const float* x   = (const float*)d_in[1];
    const float* h0  = (const float*)d_in[2];
    const float* Wih = (const float*)d_in[3];
    const float* Whh = (const float*)d_in[4];
    const float* b   = (const float*)d_in[5];
    const float* W1  = (const float*)d_in[6];
    const float* b1  = (const float*)d_in[7];
    const float* W2  = (const float*)d_in[8];
    const float* b2  = (const float*)d_in[9];
    float* out = (float*)d_out;

    cudaFuncSetAttribute(lstm_persistent_kernel,
                         cudaFuncAttributeMaxDynamicSharedMemorySize, SMEM_BYTES);
    lstm_persistent_kernel<<<NBLK, THREADS, SMEM_BYTES>>>(
        z, x, h0, Wih, Whh, b, W1, b1, W2, b2, out);
}

// round 3
// speedup vs baseline: 1.2891x; 1.1386x over previous
#include <cuda_runtime.h>

// ---------------------------------------------------------------------------
// Persistent-grid LSTM: 128 resident blocks = 16 independent batch-group
// pipelines x 8 hidden-chunk blocks. Weights SMEM-resident. Group-local
// (8-block) flag barriers instead of grid-wide atomics.
// ---------------------------------------------------------------------------

namespace {
constexpr int Bb   = 256;
constexpr int Tt   = 200;
constexpr int Fd   = 16;
constexpr int Hh   = 256;
constexpr int KTOT = 274;        // 18 (inp) + 256 (h)
constexpr int NBLK = 128;        // 16 batch groups * 8 hidden chunks
constexpr int BG   = 16;         // batch rows per group
constexpr int RB   = 128;        // gate rows per block (4 gates * 32 hidden)
constexpr int HCn  = 32;         // hidden per chunk
constexpr int THREADS = 256;
constexpr int HST  = 18;         // hdup row stride in u64 (16 batches + 2 pad)

// shared memory layout (bytes), all 16B aligned
constexpr int OFF_WS   = 0;                 // 274*128 f32          = 140288
constexpr int OFF_HDUP = 140288;            // 274*18  u64          =  39456
constexpr int OFF_W1   = 179744;            // 8*256   f32          =   8192
constexpr int OFF_GBUF = 187936;            // 16*128  f32          =   8192
constexpr int OFF_CARR = 196128;            // 512     f32          =   2048
constexpr int OFF_HB   = 198176;            // 16*256  f32          =  16384
constexpr int OFF_BSL  = 214560;            // 64      float2       =    512
constexpr int OFF_ZLOC = 215072;            // 16 f32 (pad 64)
constexpr int OFF_W2   = 215136;            // 8 f32 (pad 32)
constexpr int OFF_B1   = 215168;            // 8 f32 (pad 32)
constexpr int OFF_B2   = 215200;            // 1 f32
constexpr int OFF_TOK  = 215204;            // 1 u32 (token base)
constexpr int SMEM_BYTES = 215232;

constexpr int OUT_H = Bb * Tt;              // 51200
constexpr int OUT_C = OUT_H + Bb * Hh;      // 116736
}

__device__ unsigned g_gflag[16][8][32];     // [bg][hc][pad to 128B]
__device__ float    g_hbuf[2][Bb][Hh];
__device__ float    g_part[NBLK][BG];

typedef unsigned long long u64;

__device__ __forceinline__ u64 fma2(u64 a, u64 b, u64 c) {
    u64 d;
    asm("fma.rn.f32x2 %0, %1, %2, %3;" : "=l"(d) : "l"(a), "l"(b), "l"(c));
    return d;
}

__device__ __forceinline__ float sigf(float x) {
    return __fdividef(1.0f, 1.0f + __expf(-x));
}
__device__ __forceinline__ float tanh_(float x) {
    return 1.0f - __fdividef(2.0f, __expf(2.0f * x) + 1.0f);
}

// 8-block group barrier: parallel flag stores + acquire polls. All blocks are
// resident (1/SM at 210KB smem), so spinning is deadlock-free. Tokens are
// monotone across launches (base read from own flag at kernel start).
__device__ __forceinline__ void group_sync(int bg, int hc, unsigned tok) {
    __syncthreads();
    const int tid = threadIdx.x;
    if (tid == 0) {
        asm volatile("st.release.gpu.global.u32 [%0], %1;"
                     :: "l"(&g_gflag[bg][hc][0]), "r"(tok) : "memory");
    }
    if (tid < 8) {
        unsigned v;
        do {
            asm volatile("ld.acquire.gpu.global.u32 %0, [%1];"
                         : "=r"(v) : "l"(&g_gflag[bg][tid][0]) : "memory");
        } while ((int)(v - tok) < 0);
    }
    __syncthreads();
}

__global__ void __launch_bounds__(THREADS, 1)
lstm_persistent_kernel(const float* __restrict__ zin,  const float* __restrict__ xin,
                       const float* __restrict__ h0,   const float* __restrict__ Wih,
                       const float* __restrict__ Whh,  const float* __restrict__ bias,
                       const float* __restrict__ W1,   const float* __restrict__ b1,
                       const float* __restrict__ W2,   const float* __restrict__ b2,
                       float* __restrict__ out)
{
    extern __shared__ char smem[];
    float*  Ws    = (float*) (smem + OFF_WS);    // k-major: Ws[k*128 + r]
    u64*    hdup  = (u64*)   (smem + OFF_HDUP);  // (v,v) dup: hdup[k*HST + b]
    float*  W1s   = (float*) (smem + OFF_W1);    // W1s[f*256 + k]
    float*  gbuf  = (float*) (smem + OFF_GBUF);  // gbuf[b*128 + r]
    float*  carr  = (float*) (smem + OFF_CARR);  // c state [b*32 + j]
    float*  hb    = (float*) (smem + OFF_HB);    // phase-B h tile [b*256 + k]
    float2* bsl   = (float2*)(smem + OFF_BSL);   // bias row-pairs
    float*  zloc  = (float*) (smem + OFF_ZLOC);
    float*  W2s   = (float*) (smem + OFF_W2);
    float*  b1s   = (float*) (smem + OFF_B1);
    float*  b2s   = (float*) (smem + OFF_B2);
    unsigned* toks= (unsigned*)(smem + OFF_TOK);

    const int tid = threadIdx.x;
    const int bg  = blockIdx.x >> 3;   // batch group 0..15
    const int hc  = blockIdx.x & 7;    // hidden chunk 0..7
    const int k0  = hc * HCn;

    // ---- prologue: token base + load weight slices once ------------------
    if (tid == 0) *toks = g_gflag[bg][hc][0];
    for (int idx = tid; idx < KTOT * RB; idx += THREADS) {
        int k = idx >> 7, r = idx & 127;
        int grow = ((r >> 5) << 8) + k0 + (r & 31);       // gate*256 + k0 + j
        Ws[idx] = (k < 18) ? Wih[grow * 18 + k] : Whh[(grow << 8) + (k - 18)];
    }
    for (int idx = tid; idx < 8 * Hh; idx += THREADS)
        W1s[idx] = W1[(hc * 8 + (idx >> 8)) * Hh + (idx & 255)];
    if (tid < 64) {
        int r0 = 2 * tid, r1 = r0 + 1;
        float v0 = bias[((r0 >> 5) << 8) + k0 + (r0 & 31)];
        float v1 = bias[((r1 >> 5) << 8) + k0 + (r1 & 31)];
        bsl[tid] = make_float2(v0, v1);
    }
    if (tid < 8) { W2s[tid] = W2[hc * 8 + tid]; b1s[tid] = b1[hc * 8 + tid]; }
    if (tid == 0) *b2s = b2[0];
    for (int idx = tid; idx < BG * HCn; idx += THREADS) carr[idx] = 0.f;
    if (tid < BG) zloc[tid] = 0.f;
    __syncthreads();
    const unsigned tokbase = *toks;

    // phase-A lane geometry: warp = 32 rows x 8 batches; lane = 4 rows x 2 batches
    const int wrp = tid >> 5, lan = tid & 31;
    const int rg  = (wrp & 3) << 5;            // row group base: 0,32,64,96
    const int bgl = (wrp >> 2) << 3;           // batch group base: 0 or 8
    const int rq  = (lan & 7) << 2;            // row quad offset 0..28
    const int bp  = (lan >> 3) << 1;           // batch pair offset 0,2,4,6
    const int r0  = rg + rq;                   // first of 4 rows
    const int b0  = bgl + bp;                  // first of 2 batches
    const char* wbB = (const char*)(Ws + r0);                 // + k*512
    const char* hbB = (const char*)(hdup + b0);               // + k*144

    // ---- time loop -------------------------------------------------------
    for (int t = 0; t < Tt; ++t) {
        // finalize z_{t-1} from FF partials (redundant per block, fixed order)
        if (t > 0) {
            if (tid < BG) {
                float s = *b2s;
                #pragma unroll
                for (int c = 0; c < 8; ++c) s += __ldcg(&g_part[(bg << 3) + c][tid]);
                float zn = zloc[tid] + fmaxf(s, 0.f);
                zloc[tid] = zn;
                if (hc == 0) out[(bg * BG + tid) * Tt + (t - 1)] = zn;
            }
            __syncthreads();
        }

        // fill hdup[k][b] = (v,v): inp = [z_t, x_t(16), z_prev] ++ h_{t-1}
        {
            const int fb = tid >> 4, fl = tid & 15;
            const int bglob = bg * BG + fb;
            const float* hsrc = (t == 0) ? (h0 + bglob * Hh)
                                         : &g_hbuf[(t - 1) & 1][bglob][0];
            const float zt = zin[bglob * Tt + t];
            const float zp = zloc[fb];
            const float* xr = xin + (bglob * Tt + t) * Fd;
            for (int k = fl; k < KTOT; k += 16) {
                float v;
                if (k >= 18)      v = __ldcg(&hsrc[k - 18]);
                else if (k == 0)  v = zt;
                else if (k <= 16) v = xr[k - 1];
                else              v = zp;
                union { float2 f; u64 u; } d;
                d.f = make_float2(v, v);
                hdup[k * HST + fb] = d.u;
            }
        }
        __syncthreads();

        // phase A: g[b, r] = bias + sum_k inp/h * W
        {
            u64 a00, a01, a10, a11;
            {
                union { float2 f; u64 u; } c0, c1;
                c0.f = bsl[r0 >> 1];
                c1.f = bsl[(r0 >> 1) + 1];
                a00 = c0.u; a01 = c0.u; a10 = c1.u; a11 = c1.u;
            }
            #pragma unroll 4
            for (int k = 0; k < KTOT; ++k) {
                ulonglong2 wv = *(const ulonglong2*)(wbB + (size_t)k * 512);
                ulonglong2 hv = *(const ulonglong2*)(hbB + (size_t)k * (HST * 8));
                a00 = fma2(wv.x, hv.x, a00);
                a01 = fma2(wv.x, hv.y, a01);
                a10 = fma2(wv.y, hv.x, a10);
                a11 = fma2(wv.y, hv.y, a11);
            }
            float2* g2 = (float2*)gbuf;
            const int rp0 = r0 >> 1;
            union { u64 u; float2 f; } o;
            o.u = a00; g2[(b0    ) * 64 + rp0    ] = o.f;
            o.u = a10; g2[(b0    ) * 64 + rp0 + 1] = o.f;
            o.u = a01; g2[(b0 + 1) * 64 + rp0    ] = o.f;
            o.u = a11; g2[(b0 + 1) * 64 + rp0 + 1] = o.f;
        }
        __syncthreads();

        // gate nonlinearities + state update; publish h chunk
        {
            const int wbuf = t & 1;
            for (int idx = tid; idx < BG * HCn; idx += THREADS) {
                int b = idx >> 5, j = idx & 31;
                float gi = gbuf[(b << 7) + j];
                float gf = gbuf[(b << 7) + 32 + j];
                float gg = gbuf[(b << 7) + 64 + j];
                float go = gbuf[(b << 7) + 96 + j];
                float c = carr[idx];
                c = sigf(gf) * c + sigf(gi) * tanh_(gg);
                float h = sigf(go) * tanh_(c);
                carr[idx] = c;
                int bglob = bg * BG + b;
                g_hbuf[wbuf][bglob][k0 + j] = h;
                if (t == Tt - 1) {
                    out[OUT_H + bglob * Hh + k0 + j] = h;
                    out[OUT_C + bglob * Hh + k0 + j] = c;
                }
            }
        }
        group_sync(bg, hc, tokbase + 2 * t + 1);

        // phase B: FF head, FWD rows [hc*8, hc*8+8), all 8 warps, f32x2 split-k
        {
            const int wbuf = t & 1;
            const float4* src = (const float4*)&g_hbuf[wbuf][bg * BG][0];
            float4* dst = (float4*)hb;
            #pragma unroll
            for (int i = 0; i < BG * Hh / 4 / THREADS; ++i)
                dst[tid + i * THREADS] = __ldcg(&src[tid + i * THREADS]);
            __syncthreads();
            {
                const int b  = tid >> 4;           // 0..15
                const int f  = (tid >> 1) & 7;     // 0..7
                const int hf = tid & 1;            // k-half
                const ulonglong2* hv = (const ulonglong2*)(hb  + (b << 8) + (hf << 7));
                const ulonglong2* wv = (const ulonglong2*)(W1s + (f << 8) + (hf << 7));
                u64 ac0 = 0, ac1 = 0;
                #pragma unroll 8
                for (int q = 0; q < 32; ++q) {
                    ulonglong2 hq = hv[q], wq = wv[q];
                    ac0 = fma2(hq.x, wq.x, ac0);
                    ac1 = fma2(hq.y, wq.y, ac1);
                }
                union { u64 u; float2 f2; } u0, u1;
                u0.u = ac0; u1.u = ac1;
                float s = (u0.f2.x + u0.f2.y) + (u1.f2.x + u1.f2.y);
                s += __shfl_xor_sync(0xffffffffu, s, 1);     // combine k-halves
                float r = fmaxf(s + b1s[f], 0.f) * W2s[f];
                r += __shfl_xor_sync(0xffffffffu, r, 2);     // sum over f
                r += __shfl_xor_sync(0xffffffffu, r, 4);
                r += __shfl_xor_sync(0xffffffffu, r, 8);
                if ((tid & 15) == 0) g_part[blockIdx.x][b] = r;
            }
        }
        group_sync(bg, hc, tokbase + 2 * t + 2);
    }

    // epilogue: finalize z_{T-1}
    if (hc == 0 && tid < BG) {
        float s = *b2s;
        #pragma unroll
        for (int c = 0; c < 8; ++c) s += __ldcg(&g_part[(bg << 3) + c][tid]);
        float zn = zloc[tid] + fmaxf(s, 0.f);
        out[(bg * BG + tid) * Tt + (Tt - 1)] = zn;
    }
}

extern "C" void kernel_launch(void* const* d_in, const int* in_sizes, int n_in,
                              void* d_out, int out_size) {
    const float* z   = (const float*)d_in[0];
    const float* x   = (const float*)d_in[1];
    const float* h0  = (const float*)d_in[2];
    const float* Wih = (const float*)d_in[3];
    const float* Whh = (const float*)d_in[4];
    const float* b   = (const float*)d_in[5];
    const float* W1  = (const float*)d_in[6];
    const float* b1  = (const float*)d_in[7];
    const float* W2  = (const float*)d_in[8];
    const float* b2  = (const float*)d_in[9];
    float* out = (float*)d_out;

    cudaFuncSetAttribute(lstm_persistent_kernel,
                         cudaFuncAttributeMaxDynamicSharedMemorySize, SMEM_BYTES);
    lstm_persistent_kernel<<<NBLK, THREADS, SMEM_BYTES>>>(
        z, x, h0, Wih, Whh, b, W1, b1, W2, b2, out);
}

// round 4
// speedup vs baseline: 1.7926x; 1.3906x over previous
#include <cuda_runtime.h>

// ---------------------------------------------------------------------------
// Persistent-grid LSTM: 128 resident blocks = 16 independent batch-group
// pipelines x 8 hidden-chunk blocks. Weights SMEM-resident. ONE group barrier
// per timestep: FF head is split over k (each block contributes partials for
// all 64 FWD rows from its local h chunk); publishes are double-buffered.
// ---------------------------------------------------------------------------

namespace {
constexpr int Bb   = 256;
constexpr int Tt   = 200;
constexpr int Fd   = 16;
constexpr int Hh   = 256;
constexpr int KTOT = 274;        // 18 (inp) + 256 (h)
constexpr int NBLK = 128;        // 16 batch groups * 8 hidden chunks
constexpr int BG   = 16;         // batch rows per group
constexpr int RB   = 128;        // gate rows per block (4 gates * 32 hidden)
constexpr int HCn  = 32;         // hidden per chunk
constexpr int FWD  = 64;
constexpr int THREADS = 256;
constexpr int HST  = 18;         // hdup row stride in u64 (16 batches + 2 pad)

// shared memory layout (bytes), all 16B aligned
constexpr int OFF_WS   = 0;                 // 274*128 f32   = 140288
constexpr int OFF_HDUP = 140288;            // 274*18  u64   =  39456 -> 179744
constexpr int OFF_W1KT = 179744;            // 32*64   f32   =   8192 -> 187936
constexpr int OFF_GBUF = 187936;            // 16*128  f32   =   8192 -> 196128
constexpr int OFF_CARR = 196128;            // 512     f32   =   2048 -> 198176
constexpr int OFF_HLOC = 198176;            // 16*32   f32   =   2048 -> 200224
constexpr int OFF_BSL  = 200224;            // 64      float2=    512 -> 200736
constexpr int OFF_B1F  = 200736;            // 64      f32   =    256 -> 200992
constexpr int OFF_W2F  = 200992;            // 64      f32   =    256 -> 201248
constexpr int OFF_ZLOC = 201248;            // 16      f32 (pad 64)   -> 201312
constexpr int OFF_B2   = 201312;            // 1 f32
constexpr int OFF_TOK  = 201316;            // 1 u32
constexpr int SMEM_BYTES = 201344;

constexpr int OUT_H = Bb * Tt;              // 51200
constexpr int OUT_C = OUT_H + Bb * Hh;      // 116736
}

__device__ unsigned g_gflag[16][8][32];           // [bg][hc][pad to 128B]
__device__ float    g_hpub[2][16][8][BG * HCn];   // published h chunks
__device__ float    g_ff  [2][16][8][BG * FWD];   // FF k-partials [b][f]

typedef unsigned long long u64;

__device__ __forceinline__ u64 fma2(u64 a, u64 b, u64 c) {
    u64 d;
    asm("fma.rn.f32x2 %0, %1, %2, %3;" : "=l"(d) : "l"(a), "l"(b), "l"(c));
    return d;
}

__device__ __forceinline__ float sigf(float x) {
    return __fdividef(1.0f, 1.0f + __expf(-x));
}
__device__ __forceinline__ float tanh_(float x) {
    return 1.0f - __fdividef(2.0f, __expf(2.0f * x) + 1.0f);
}

// 8-block group barrier: parallel flag stores + acquire polls. All blocks
// resident (1/SM), so spinning is deadlock-free. Tokens monotone across
// launches (base read from own flag at kernel start; every launch adds Tt).
__device__ __forceinline__ void group_sync(int bg, int hc, unsigned tok) {
    __syncthreads();
    const int tid = threadIdx.x;
    if (tid == 0) {
        asm volatile("st.release.gpu.global.u32 [%0], %1;"
                     :: "l"(&g_gflag[bg][hc][0]), "r"(tok) : "memory");
    }
    if (tid < 8) {
        unsigned v;
        do {
            asm volatile("ld.acquire.gpu.global.u32 %0, [%1];"
                         : "=r"(v) : "l"(&g_gflag[bg][tid][0]) : "memory");
        } while ((int)(v - tok) < 0);
    }
    __syncthreads();
}

__global__ void __launch_bounds__(THREADS, 1)
lstm_persistent_kernel(const float* __restrict__ zin,  const float* __restrict__ xin,
                       const float* __restrict__ h0,   const float* __restrict__ Wih,
                       const float* __restrict__ Whh,  const float* __restrict__ bias,
                       const float* __restrict__ W1,   const float* __restrict__ b1,
                       const float* __restrict__ W2,   const float* __restrict__ b2,
                       float* __restrict__ out)
{
    extern __shared__ char smem[];
    float*  Ws    = (float*) (smem + OFF_WS);    // k-major: Ws[k*128 + r]
    u64*    hdup  = (u64*)   (smem + OFF_HDUP);  // (v,v) dup: hdup[k*HST + b]
    float*  W1kT  = (float*) (smem + OFF_W1KT);  // W1kT[j*64 + f], j in chunk
    float*  gbuf  = (float*) (smem + OFF_GBUF);  // gbuf[b*128 + r]
    float*  carr  = (float*) (smem + OFF_CARR);  // c state [b*32 + j]
    float*  hloc  = (float*) (smem + OFF_HLOC);  // local h chunk [b*32 + j]
    float2* bsl   = (float2*)(smem + OFF_BSL);   // bias row-pairs
    float*  b1f   = (float*) (smem + OFF_B1F);
    float*  W2f   = (float*) (smem + OFF_W2F);
    float*  zloc  = (float*) (smem + OFF_ZLOC);
    float*  b2s   = (float*) (smem + OFF_B2);
    unsigned* toks= (unsigned*)(smem + OFF_TOK);

    const int tid = threadIdx.x;
    const int bg  = blockIdx.x >> 3;   // batch group 0..15
    const int hc  = blockIdx.x & 7;    // hidden chunk 0..7
    const int k0  = hc * HCn;

    // ---- prologue: token base + load weight slices once ------------------
    if (tid == 0) *toks = g_gflag[bg][hc][0];
    for (int idx = tid; idx < KTOT * RB; idx += THREADS) {
        int k = idx >> 7, r = idx & 127;
        int grow = ((r >> 5) << 8) + k0 + (r & 31);       // gate*256 + k0 + j
        Ws[idx] = (k < 18) ? Wih[grow * 18 + k] : Whh[(grow << 8) + (k - 18)];
    }
    for (int idx = tid; idx < HCn * FWD; idx += THREADS) {
        int j = idx >> 6, f = idx & 63;
        W1kT[idx] = W1[f * Hh + k0 + j];
    }
    if (tid < 64) {
        int r0 = 2 * tid, r1 = r0 + 1;
        float v0 = bias[((r0 >> 5) << 8) + k0 + (r0 & 31)];
        float v1 = bias[((r1 >> 5) << 8) + k0 + (r1 & 31)];
        bsl[tid] = make_float2(v0, v1);
        b1f[tid] = b1[tid];
        W2f[tid] = W2[tid];
    }
    if (tid == 0) *b2s = b2[0];
    for (int idx = tid; idx < BG * HCn; idx += THREADS) carr[idx] = 0.f;
    if (tid < BG) zloc[tid] = 0.f;
    __syncthreads();
    const unsigned tokbase = *toks;

    // phase-A lane geometry: warp = 32 rows x 8 batches; lane = 4 rows x 2 batches
    const int wrp = tid >> 5, lan = tid & 31;
    const int rg  = (wrp & 3) << 5;            // row group base: 0,32,64,96
    const int bgl = (wrp >> 2) << 3;           // batch group base: 0 or 8
    const int rq  = (lan & 7) << 2;            // row quad offset 0..28
    const int bp  = (lan >> 3) << 1;           // batch pair offset 0,2,4,6
    const int r0  = rg + rq;                   // first of 4 rows
    const int b0  = bgl + bp;                  // first of 2 batches
    const char* wbB = (const char*)(Ws + r0);                 // + k*512
    const char* hbB = (const char*)(hdup + b0);               // + k*144

    // FF-partial lane geometry
    const int pf  = tid & 63;                  // FWD row 0..63
    const int pbq = tid >> 6;                  // batch quad 0..3

    // z-finalize lane geometry: b = tid>>4, 16 lanes each handle 4 f's
    const int zb = tid >> 4, zl = tid & 15;

    // ---- time loop -------------------------------------------------------
    for (int t = 0; t < Tt; ++t) {
        const int pb = (t - 1) & 1;   // buffer holding step t-1 publishes
        const int cb = t & 1;         // buffer for this step's publishes

        // finalize z_{t-1}: reduce 8 chunks' FF partials, relu, W2, relu
        if (t > 0) {
            float a0 = 0.f, a1 = 0.f, a2 = 0.f, a3 = 0.f;
            const float* base = &g_ff[pb][bg][0][zb * FWD + zl * 4];
            #pragma unroll
            for (int c = 0; c < 8; ++c) {
                float4 v = __ldcg((const float4*)(base + c * (BG * FWD)));
                a0 += v.x; a1 += v.y; a2 += v.z; a3 += v.w;
            }
            int f4 = zl * 4;
            float s = fmaxf(a0 + b1f[f4], 0.f)     * W2f[f4]
                    + fmaxf(a1 + b1f[f4 + 1], 0.f) * W2f[f4 + 1]
                    + fmaxf(a2 + b1f[f4 + 2], 0.f) * W2f[f4 + 2]
                    + fmaxf(a3 + b1f[f4 + 3], 0.f) * W2f[f4 + 3];
            s += __shfl_xor_sync(0xffffffffu, s, 1);
            s += __shfl_xor_sync(0xffffffffu, s, 2);
            s += __shfl_xor_sync(0xffffffffu, s, 4);
            s += __shfl_xor_sync(0xffffffffu, s, 8);
            if (zl == 0) {
                float zn = zloc[zb] + fmaxf(s + *b2s, 0.f);
                zloc[zb] = zn;
                if (hc == 0) out[(bg * BG + zb) * Tt + (t - 1)] = zn;
            }
            __syncthreads();
        }

        // fill hdup[k][b] = (v,v): inp = [z_t, x_t(16), z_prev] ++ h_{t-1}
        {
            const int fb = tid >> 4, fl = tid & 15;
            const int bglob = bg * BG + fb;
            const float zt = zin[bglob * Tt + t];
            const float zp = zloc[fb];
            const float* xr = xin + (bglob * Tt + t) * Fd;
            if (t == 0) {
                const float* hsrc = h0 + bglob * Hh;
                for (int k = fl; k < KTOT; k += 16) {
                    float v;
                    if (k >= 18)      v = hsrc[k - 18];
                    else if (k == 0)  v = zt;
                    else if (k <= 16) v = xr[k - 1];
                    else              v = zp;
                    union { float2 f; u64 u; } d;
                    d.f = make_float2(v, v);
                    hdup[k * HST + fb] = d.u;
                }
            } else {
                const float* hsrc = &g_hpub[pb][bg][0][fb * HCn];
                for (int k = fl; k < KTOT; k += 16) {
                    float v;
                    if (k >= 18) {
                        int kk = k - 18;
                        int c = kk >> 5, j = kk & 31;
                        v = __ldcg(&hsrc[c * (BG * HCn) + j]);
                    }
                    else if (k == 0)  v = zt;
                    else if (k <= 16) v = xr[k - 1];
                    else              v = zp;
                    union { float2 f; u64 u; } d;
                    d.f = make_float2(v, v);
                    hdup[k * HST + fb] = d.u;
                }
            }
        }
        __syncthreads();

        // phase A: g[b, r] = bias + sum_k inp/h * W
        {
            u64 a00, a01, a10, a11;
            {
                union { float2 f; u64 u; } c0, c1;
                c0.f = bsl[r0 >> 1];
                c1.f = bsl[(r0 >> 1) + 1];
                a00 = c0.u; a01 = c0.u; a10 = c1.u; a11 = c1.u;
            }
            #pragma unroll 4
            for (int k = 0; k < KTOT; ++k) {
                ulonglong2 wv = *(const ulonglong2*)(wbB + (size_t)k * 512);
                ulonglong2 hv = *(const ulonglong2*)(hbB + (size_t)k * (HST * 8));
                a00 = fma2(wv.x, hv.x, a00);
                a01 = fma2(wv.x, hv.y, a01);
                a10 = fma2(wv.y, hv.x, a10);
                a11 = fma2(wv.y, hv.y, a11);
            }
            float2* g2 = (float2*)gbuf;
            const int rp0 = r0 >> 1;
            union { u64 u; float2 f; } o;
            o.u = a00; g2[(b0    ) * 64 + rp0    ] = o.f;
            o.u = a10; g2[(b0    ) * 64 + rp0 + 1] = o.f;
            o.u = a01; g2[(b0 + 1) * 64 + rp0    ] = o.f;
            o.u = a11; g2[(b0 + 1) * 64 + rp0 + 1] = o.f;
        }
        __syncthreads();

        // gate nonlinearities + state update; h -> hloc (smem) + publish chunk
        {
            float* hp = &g_hpub[cb][bg][hc][0];
            for (int idx = tid; idx < BG * HCn; idx += THREADS) {
                int b = idx >> 5, j = idx & 31;
                float gi = gbuf[(b << 7) + j];
                float gf = gbuf[(b << 7) + 32 + j];
                float gg = gbuf[(b << 7) + 64 + j];
                float go = gbuf[(b << 7) + 96 + j];
                float c = carr[idx];
                c = sigf(gf) * c + sigf(gi) * tanh_(gg);
                float h = sigf(go) * tanh_(c);
                carr[idx] = c;
                hloc[idx] = h;
                hp[idx] = h;
                if (t == Tt - 1) {
                    int bglob = bg * BG + b;
                    out[OUT_H + bglob * Hh + k0 + j] = h;
                    out[OUT_C + bglob * Hh + k0 + j] = c;
                }
            }
        }
        __syncthreads();

        // FF k-partials: part[b][f] = sum_j W1[f][k0+j] * h[b][j], all 64 f
        {
            float ac0 = 0.f, ac1 = 0.f, ac2 = 0.f, ac3 = 0.f;
            const float4* h4 = (const float4*)hloc;
            #pragma unroll
            for (int jq = 0; jq < 8; ++jq) {
                float4 hq0 = h4[(pbq * 4 + 0) * 8 + jq];
                float4 hq1 = h4[(pbq * 4 + 1) * 8 + jq];
                float4 hq2 = h4[(pbq * 4 + 2) * 8 + jq];
                float4 hq3 = h4[(pbq * 4 + 3) * 8 + jq];
                float w0 = W1kT[(jq * 4 + 0) * 64 + pf];
                float w1 = W1kT[(jq * 4 + 1) * 64 + pf];
                float w2 = W1kT[(jq * 4 + 2) * 64 + pf];
                float w3 = W1kT[(jq * 4 + 3) * 64 + pf];
                ac0 = fmaf(hq0.x, w0, ac0); ac0 = fmaf(hq0.y, w1, ac0);
                ac0 = fmaf(hq0.z, w2, ac0); ac0 = fmaf(hq0.w, w3, ac0);
                ac1 = fmaf(hq1.x, w0, ac1); ac1 = fmaf(hq1.y, w1, ac1);
                ac1 = fmaf(hq1.z, w2, ac1); ac1 = fmaf(hq1.w, w3, ac1);
                ac2 = fmaf(hq2.x, w0, ac2); ac2 = fmaf(hq2.y, w1, ac2);
                ac2 = fmaf(hq2.z, w2, ac2); ac2 = fmaf(hq2.w, w3, ac2);
                ac3 = fmaf(hq3.x, w0, ac3); ac3 = fmaf(hq3.y, w1, ac3);
                ac3 = fmaf(hq3.z, w2, ac3); ac3 = fmaf(hq3.w, w3, ac3);
            }
            float* fp = &g_ff[cb][bg][hc][0];
            fp[(pbq * 4 + 0) * FWD + pf] = ac0;
            fp[(pbq * 4 + 1) * FWD + pf] = ac1;
            fp[(pbq * 4 + 2) * FWD + pf] = ac2;
            fp[(pbq * 4 + 3) * FWD + pf] = ac3;
        }

        group_sync(bg, hc, tokbase + t + 1);
    }

    // epilogue: finalize z_{T-1}
    {
        const int pb = (Tt - 1) & 1;
        if (hc == 0) {
            float a0 = 0.f, a1 = 0.f, a2 = 0.f, a3 = 0.f;
            const float* base = &g_ff[pb][bg][0][zb * FWD + zl * 4];
            #pragma unroll
            for (int c = 0; c < 8; ++c) {
                float4 v = __ldcg((const float4*)(base + c * (BG * FWD)));
                a0 += v.x; a1 += v.y; a2 += v.z; a3 += v.w;
            }
            int f4 = zl * 4;
            float s = fmaxf(a0 + b1f[f4], 0.f)     * W2f[f4]
                    + fmaxf(a1 + b1f[f4 + 1], 0.f) * W2f[f4 + 1]
                    + fmaxf(a2 + b1f[f4 + 2], 0.f) * W2f[f4 + 2]
                    + fmaxf(a3 + b1f[f4 + 3], 0.f) * W2f[f4 + 3];
            s += __shfl_xor_sync(0xffffffffu, s, 1);
            s += __shfl_xor_sync(0xffffffffu, s, 2);
            s += __shfl_xor_sync(0xffffffffu, s, 4);
            s += __shfl_xor_sync(0xffffffffu, s, 8);
            if (zl == 0) {
                float zn = zloc[zb] + fmaxf(s + *b2s, 0.f);
                out[(bg * BG + zb) * Tt + (Tt - 1)] = zn;
            }
        }
    }
}

extern "C" void kernel_launch(void* const* d_in, const int* in_sizes, int n_in,
                              void* d_out, int out_size) {
    const float* z   = (const float*)d_in[0];
    const float* x   = (const float*)d_in[1];
    const float* h0  = (const float*)d_in[2];
    const float* Wih = (const float*)d_in[3];
    const float* Whh = (const float*)d_in[4];
    const float* b   = (const float*)d_in[5];
    const float* W1  = (const float*)d_in[6];
    const float* b1  = (const float*)d_in[7];
    const float* W2  = (const float*)d_in[8];
    const float* b2  = (const float*)d_in[9];
    float* out = (float*)d_out;

    cudaFuncSetAttribute(lstm_persistent_kernel,
                         cudaFuncAttributeMaxDynamicSharedMemorySize, SMEM_BYTES);
    lstm_persistent_kernel<<<NBLK, THREADS, SMEM_BYTES>>>(
        z, x, h0, Wih, Whh, b, W1, b1, W2, b2, out);
}

// round 6
// speedup vs baseline: 1.8024x; 1.0054x over previous
#include <cuda_runtime.h>

// ---------------------------------------------------------------------------
// Persistent-grid LSTM: 128 resident blocks = 16 independent batch-group
// pipelines x 8 hidden-chunk blocks. Weights SMEM-resident. NO barriers:
// pure dataflow via per-block flags; phase A is segmented per source chunk
// and software-pipelined so peer-publish latency hides under FMA work.
// ---------------------------------------------------------------------------

namespace {
constexpr int Bb   = 256;
constexpr int Tt   = 200;
constexpr int Fd   = 16;
constexpr int Hh   = 256;
constexpr int KTOT = 274;        // 18 (inp) + 256 (h)
constexpr int NBLK = 128;        // 16 batch groups * 8 hidden chunks
constexpr int BG   = 16;         // batch rows per group
constexpr int RB   = 128;        // gate rows per block (4 gates * 32 hidden)
constexpr int HCn  = 32;         // hidden per chunk
constexpr int FWD  = 64;
constexpr int THREADS = 256;
constexpr int HST  = 18;         // hdup row stride in u64 (16 batches + 2 pad)

// shared memory layout (bytes), all 16B aligned
constexpr int OFF_WS   = 0;                 // 274*128 f32   = 140288
constexpr int OFF_HDUP = 140288;            // 274*18  u64   =  39456 -> 179744
constexpr int OFF_W1KT = 179744;            // 32*64   f32   =   8192 -> 187936
constexpr int OFF_GBUF = 187936;            // 16*128  f32   =   8192 -> 196128
constexpr int OFF_CARR = 196128;            // 512     f32   =   2048 -> 198176
constexpr int OFF_HLOC = 198176;            // 16*32   f32   =   2048 -> 200224
constexpr int OFF_BSL  = 200224;            // 64      float2=    512 -> 200736
constexpr int OFF_B1F  = 200736;            // 64      f32   =    256 -> 200992
constexpr int OFF_W2F  = 200992;            // 64      f32   =    256 -> 201248
constexpr int OFF_ZLOC = 201248;            // 16      f32 (pad 64)   -> 201312
constexpr int OFF_B2   = 201312;            // 1 f32
constexpr int OFF_TOK  = 201316;            // 1 u32
constexpr int SMEM_BYTES = 201344;

constexpr int OUT_H = Bb * Tt;              // 51200
constexpr int OUT_C = OUT_H + Bb * Hh;      // 116736
}

__device__ unsigned g_gflag[16][8][32];           // [bg][hc][pad to 128B]
__device__ float    g_hpub[2][16][8][BG * HCn];   // published h chunks [b*32+j]
__device__ float    g_ff  [2][16][8][BG * FWD];   // FF k-partials [b][f]

typedef unsigned long long u64;

__device__ __forceinline__ u64 fma2(u64 a, u64 b, u64 c) {
    u64 d;
    asm("fma.rn.f32x2 %0, %1, %2, %3;" : "=l"(d) : "l"(a), "l"(b), "l"(c));
    return d;
}

__device__ __forceinline__ float sigf(float x) {
    return __fdividef(1.0f, 1.0f + __expf(-x));
}
__device__ __forceinline__ float tanh_(float x) {
    return 1.0f - __fdividef(2.0f, __expf(2.0f * x) + 1.0f);
}

__device__ __forceinline__ unsigned ld_acq(const unsigned* p) {
    unsigned v;
    asm volatile("ld.acquire.gpu.global.u32 %0, [%1];"
                 : "=r"(v) : "l"(p) : "memory");
    return v;
}
__device__ __forceinline__ void st_rel(unsigned* p, unsigned v) {
    asm volatile("st.release.gpu.global.u32 [%0], %1;"
                 :: "l"(p), "r"(v) : "memory");
}

// wait until all 7 peer flags reach `need`; fast path is a single pass.
__device__ __forceinline__ void wait_peers(int bg, int hc, unsigned need) {
    bool ok = true;
    #pragma unroll
    for (int p = 1; p < 8; ++p)
        ok &= ((int)(ld_acq(&g_gflag[bg][(hc + p) & 7][0]) - need) >= 0);
    if (ok) return;
    for (;;) {
        __nanosleep(32);
        ok = true;
        #pragma unroll
        for (int p = 1; p < 8; ++p)
            ok &= ((int)(ld_acq(&g_gflag[bg][(hc + p) & 7][0]) - need) >= 0);
        if (ok) return;
    }
}

__global__ void __launch_bounds__(THREADS, 1)
lstm_persistent_kernel(const float* __restrict__ zin,  const float* __restrict__ xin,
                       const float* __restrict__ h0,   const float* __restrict__ Wih,
                       const float* __restrict__ Whh,  const float* __restrict__ bias,
                       const float* __restrict__ W1,   const float* __restrict__ b1,
                       const float* __restrict__ W2,   const float* __restrict__ b2,
                       float* __restrict__ out)
{
    extern __shared__ char smem[];
    float*  Ws    = (float*) (smem + OFF_WS);    // k-major: Ws[k*128 + r]
    u64*    hdup  = (u64*)   (smem + OFF_HDUP);  // (v,v) dup: hdup[k*HST + b]
    float*  W1kT  = (float*) (smem + OFF_W1KT);  // W1kT[j*64 + f]
    float*  gbuf  = (float*) (smem + OFF_GBUF);  // gbuf[b*128 + r]
    float*  carr  = (float*) (smem + OFF_CARR);  // c state [b*32 + j]
    float*  hloc  = (float*) (smem + OFF_HLOC);  // local h chunk [b*32 + j]
    float2* bsl   = (float2*)(smem + OFF_BSL);   // bias row-pairs
    float*  b1f   = (float*) (smem + OFF_B1F);
    float*  W2f   = (float*) (smem + OFF_W2F);
    float*  zloc  = (float*) (smem + OFF_ZLOC);
    float*  b2s   = (float*) (smem + OFF_B2);
    unsigned* toks= (unsigned*)(smem + OFF_TOK);

    const int tid = threadIdx.x;
    const int bg  = blockIdx.x >> 3;   // batch group 0..15
    const int hc  = blockIdx.x & 7;    // hidden chunk 0..7
    const int k0  = hc * HCn;

    // ---- prologue: token base + load weight slices once ------------------
    if (tid == 0) *toks = g_gflag[bg][hc][0];
    for (int idx = tid; idx < KTOT * RB; idx += THREADS) {
        int k = idx >> 7, r = idx & 127;
        int grow = ((r >> 5) << 8) + k0 + (r & 31);       // gate*256 + k0 + j
        Ws[idx] = (k < 18) ? Wih[grow * 18 + k] : Whh[(grow << 8) + (k - 18)];
    }
    for (int idx = tid; idx < HCn * FWD; idx += THREADS) {
        int j = idx >> 6, f = idx & 63;
        W1kT[idx] = W1[f * Hh + k0 + j];
    }
    if (tid < 64) {
        int r0i = 2 * tid, r1i = r0i + 1;
        float v0 = bias[((r0i >> 5) << 8) + k0 + (r0i & 31)];
        float v1 = bias[((r1i >> 5) << 8) + k0 + (r1i & 31)];
        bsl[tid] = make_float2(v0, v1);
        b1f[tid] = b1[tid];
        W2f[tid] = W2[tid];
    }
    if (tid == 0) *b2s = b2[0];
    for (int idx = tid; idx < BG * HCn; idx += THREADS) carr[idx] = 0.f;
    if (tid < BG) zloc[tid] = 0.f;
    __syncthreads();
    const unsigned tokbase = *toks;

    // phase-A lane geometry: warp = 32 rows x 8 batches; lane = 4 rows x 2 batches
    const int wrp = tid >> 5, lan = tid & 31;
    const int rg  = (wrp & 3) << 5;            // row group base: 0,32,64,96
    const int bgl = (wrp >> 2) << 3;           // batch group base: 0 or 8
    const int rq  = (lan & 7) << 2;            // row quad offset 0..28
    const int bp  = (lan >> 3) << 1;           // batch pair offset 0,2,4,6
    const int r0  = rg + rq;                   // first of 4 rows
    const int b0  = bgl + bp;                  // first of 2 batches
    const char* wbB = (const char*)(Ws + r0);                 // + k*512
    const char* hbB = (const char*)(hdup + b0);               // + k*144

    // fill lane geometry
    const int fb = tid >> 4, fl = tid & 15;
    // FF-partial lane geometry
    const int pf  = tid & 63;                  // FWD row 0..63
    const int pbq = tid >> 6;                  // batch quad 0..3
    // z-finalize lane geometry
    const int zb = tid >> 4, zl = tid & 15;

    // ---- time loop -------------------------------------------------------
    for (int t = 0; t < Tt; ++t) {
        const int pb = (t - 1) & 1;   // buffer holding step t-1 publishes
        const int cb = t & 1;         // buffer for this step's publishes
        const int bglob = bg * BG + fb;

        // S_in fill: k = 0..16 (k=17 = z_prev handled as late rank-1 update)
        {
            const float zt = zin[bglob * Tt + t];
            const float* xr = xin + (bglob * Tt + t) * Fd;
            float v = (fl == 0) ? zt : xr[fl - 1];
            union { float2 f; u64 u; } d;
            d.f = make_float2(v, v);
            hdup[fl * HST + fb] = d.u;
            if (fl == 0) {
                d.f = make_float2(xr[15], xr[15]);
                hdup[16 * HST + fb] = d.u;
            }
        }

        // accumulators (bias preloaded)
        u64 a00, a01, a10, a11;
        {
            union { float2 f; u64 u; } c0, c1;
            c0.f = bsl[r0 >> 1];
            c1.f = bsl[(r0 >> 1) + 1];
            a00 = c0.u; a01 = c0.u; a10 = c1.u; a11 = c1.u;
        }
        auto fma_range = [&](int kbase, int n) {
            #pragma unroll 8
            for (int kk = 0; kk < n; ++kk) {
                int k = kbase + kk;
                ulonglong2 wv = *(const ulonglong2*)(wbB + (size_t)k * 512);
                ulonglong2 hv = *(const ulonglong2*)(hbB + (size_t)k * (HST * 8));
                a00 = fma2(wv.x, hv.x, a00);
                a01 = fma2(wv.x, hv.y, a01);
                a10 = fma2(wv.y, hv.x, a10);
                a11 = fma2(wv.y, hv.y, a11);
            }
        };

        float pa0 = 0.f, pa1 = 0.f, pa2 = 0.f, pa3 = 0.f;

        if (t == 0) {
            // fill all h segments from h0; no peer deps, no partials
            const float* hsrc = h0 + bglob * Hh;
            for (int k = fl; k < KTOT; k += 16) {
                if (k >= 18) {
                    float v = hsrc[k - 18];
                    union { float2 f; u64 u; } d;
                    d.f = make_float2(v, v);
                    hdup[k * HST + fb] = d.u;
                }
            }
            __syncthreads();
            fma_range(0, 17);
            fma_range(18, 256);
        } else {
            // wait for all 7 peer flags (steady state: already set)
            wait_peers(bg, hc, tokbase + t);
            // own FF partials (own publish, no flag needed)
            {
                float4 v = __ldcg((const float4*)&g_ff[pb][bg][hc][zb * FWD + zl * 4]);
                pa0 = v.x; pa1 = v.y; pa2 = v.z; pa3 = v.w;
            }
            // fill first peer segment
            {
                int c1 = (hc + 1) & 7;
                const float* src = &g_hpub[pb][bg][c1][fb * 32];
                float v0 = __ldcg(src + fl);
                float v1 = __ldcg(src + fl + 16);
                union { float2 f; u64 u; } d;
                int kb = 18 + 32 * c1;
                d.f = make_float2(v0, v0); hdup[(kb + fl) * HST + fb] = d.u;
                d.f = make_float2(v1, v1); hdup[(kb + fl + 16) * HST + fb] = d.u;
            }
            __syncthreads();

            // iteration 1: FMA S_in + own seg; prefetch peer 2; partials of peer 1
            {
                int c2 = (hc + 2) & 7, c1 = (hc + 1) & 7;
                const float* src = &g_hpub[pb][bg][c2][fb * 32];
                float v0 = __ldcg(src + fl);
                float v1 = __ldcg(src + fl + 16);
                float4 pv = __ldcg((const float4*)&g_ff[pb][bg][c1][zb * FWD + zl * 4]);
                fma_range(0, 17);
                fma_range(18 + 32 * hc, 32);
                pa0 += pv.x; pa1 += pv.y; pa2 += pv.z; pa3 += pv.w;
                union { float2 f; u64 u; } d;
                int kb = 18 + 32 * c2;
                d.f = make_float2(v0, v0); hdup[(kb + fl) * HST + fb] = d.u;
                d.f = make_float2(v1, v1); hdup[(kb + fl + 16) * HST + fb] = d.u;
                __syncthreads();
            }
            // iterations 2..6: FMA peer j-1; prefetch peer j+1; partials of peer j
            for (int j = 2; j <= 6; ++j) {
                int cpre  = (hc + j + 1) & 7;
                int cthis = (hc + j) & 7;
                int cfma  = (hc + j - 1) & 7;
                const float* src = &g_hpub[pb][bg][cpre][fb * 32];
                float v0 = __ldcg(src + fl);
                float v1 = __ldcg(src + fl + 16);
                float4 pv = __ldcg((const float4*)&g_ff[pb][bg][cthis][zb * FWD + zl * 4]);
                fma_range(18 + 32 * cfma, 32);
                pa0 += pv.x; pa1 += pv.y; pa2 += pv.z; pa3 += pv.w;
                union { float2 f; u64 u; } d;
                int kb = 18 + 32 * cpre;
                d.f = make_float2(v0, v0); hdup[(kb + fl) * HST + fb] = d.u;
                d.f = make_float2(v1, v1); hdup[(kb + fl + 16) * HST + fb] = d.u;
                __syncthreads();
            }
            // tail: FMA peer 6 (partials of peer 7 overlap), then FMA peer 7
            {
                int c7 = (hc + 7) & 7, c6 = (hc + 6) & 7;
                float4 pv = __ldcg((const float4*)&g_ff[pb][bg][c7][zb * FWD + zl * 4]);
                fma_range(18 + 32 * c6, 32);
                pa0 += pv.x; pa1 += pv.y; pa2 += pv.z; pa3 += pv.w;
                fma_range(18 + 32 * c7, 32);
            }
        }

        // finalize z_{t-1} from accumulated partials
        if (t > 0) {
            int f4 = zl * 4;
            float s = fmaxf(pa0 + b1f[f4], 0.f)     * W2f[f4]
                    + fmaxf(pa1 + b1f[f4 + 1], 0.f) * W2f[f4 + 1]
                    + fmaxf(pa2 + b1f[f4 + 2], 0.f) * W2f[f4 + 2]
                    + fmaxf(pa3 + b1f[f4 + 3], 0.f) * W2f[f4 + 3];
            s += __shfl_xor_sync(0xffffffffu, s, 1);
            s += __shfl_xor_sync(0xffffffffu, s, 2);
            s += __shfl_xor_sync(0xffffffffu, s, 4);
            s += __shfl_xor_sync(0xffffffffu, s, 8);
            if (zl == 0) {
                float zn = zloc[zb] + fmaxf(s + *b2s, 0.f);
                zloc[zb] = zn;
                if (hc == 0) out[(bg * BG + zb) * Tt + (t - 1)] = zn;
            }
        }
        __syncthreads();

        // k=17 rank-1 update (z_prev) + store g to smem
        {
            union { float2 f; u64 u; } zz0, zz1;
            float zv0 = zloc[b0], zv1 = zloc[b0 + 1];
            zz0.f = make_float2(zv0, zv0);
            zz1.f = make_float2(zv1, zv1);
            ulonglong2 wv = *(const ulonglong2*)(wbB + (size_t)17 * 512);
            a00 = fma2(wv.x, zz0.u, a00);
            a10 = fma2(wv.y, zz0.u, a10);
            a01 = fma2(wv.x, zz1.u, a01);
            a11 = fma2(wv.y, zz1.u, a11);

            float2* g2 = (float2*)gbuf;
            const int rp0 = r0 >> 1;
            union { u64 u; float2 f; } o;
            o.u = a00; g2[(b0    ) * 64 + rp0    ] = o.f;
            o.u = a10; g2[(b0    ) * 64 + rp0 + 1] = o.f;
            o.u = a01; g2[(b0 + 1) * 64 + rp0    ] = o.f;
            o.u = a11; g2[(b0 + 1) * 64 + rp0 + 1] = o.f;
        }
        __syncthreads();

        // gates + state update; h -> hloc + own hdup segment (dup) + publish
        {
            float* hp = &g_hpub[cb][bg][hc][0];
            for (int idx = tid; idx < BG * HCn; idx += THREADS) {
                int b = idx >> 5, j = idx & 31;
                float gi = gbuf[(b << 7) + j];
                float gf = gbuf[(b << 7) + 32 + j];
                float gg = gbuf[(b << 7) + 64 + j];
                float go = gbuf[(b << 7) + 96 + j];
                float c = carr[idx];
                c = sigf(gf) * c + sigf(gi) * tanh_(gg);
                float h = sigf(go) * tanh_(c);
                carr[idx] = c;
                hloc[idx] = h;
                union { float2 f; u64 u; } d;
                d.f = make_float2(h, h);
                hdup[(18 + k0 + j) * HST + b] = d.u;   // own seg for next step
                hp[idx] = h;
                if (t == Tt - 1) {
                    int bb = bg * BG + b;
                    out[OUT_H + bb * Hh + k0 + j] = h;
                    out[OUT_C + bb * Hh + k0 + j] = c;
                }
            }
        }
        __syncthreads();

        // FF k-partials: part[b][f] = sum_j W1[f][k0+j] * h[b][j], all 64 f
        {
            float ac0 = 0.f, ac1 = 0.f, ac2 = 0.f, ac3 = 0.f;
            const float4* h4 = (const float4*)hloc;
            #pragma unroll
            for (int jq = 0; jq < 8; ++jq) {
                float4 hq0 = h4[(pbq * 4 + 0) * 8 + jq];
                float4 hq1 = h4[(pbq * 4 + 1) * 8 + jq];
                float4 hq2 = h4[(pbq * 4 + 2) * 8 + jq];
                float4 hq3 = h4[(pbq * 4 + 3) * 8 + jq];
                float w0 = W1kT[(jq * 4 + 0) * 64 + pf];
                float w1 = W1kT[(jq * 4 + 1) * 64 + pf];
                float w2 = W1kT[(jq * 4 + 2) * 64 + pf];
                float w3 = W1kT[(jq * 4 + 3) * 64 + pf];
                ac0 = fmaf(hq0.x, w0, ac0); ac0 = fmaf(hq0.y, w1, ac0);
                ac0 = fmaf(hq0.z, w2, ac0); ac0 = fmaf(hq0.w, w3, ac0);
                ac1 = fmaf(hq1.x, w0, ac1); ac1 = fmaf(hq1.y, w1, ac1);
                ac1 = fmaf(hq1.z, w2, ac1); ac1 = fmaf(hq1.w, w3, ac1);
                ac2 = fmaf(hq2.x, w0, ac2); ac2 = fmaf(hq2.y, w1, ac2);
                ac2 = fmaf(hq2.z, w2, ac2); ac2 = fmaf(hq2.w, w3, ac2);
                ac3 = fmaf(hq3.x, w0, ac3); ac3 = fmaf(hq3.y, w1, ac3);
                ac3 = fmaf(hq3.z, w2, ac3); ac3 = fmaf(hq3.w, w3, ac3);
            }
            float* fp = &g_ff[cb][bg][hc][0];
            fp[(pbq * 4 + 0) * FWD + pf] = ac0;
            fp[(pbq * 4 + 1) * FWD + pf] = ac1;
            fp[(pbq * 4 + 2) * FWD + pf] = ac2;
            fp[(pbq * 4 + 3) * FWD + pf] = ac3;
        }
        __syncthreads();                       // publishes complete block-wide
        if (tid == 0) st_rel(&g_gflag[bg][hc][0], tokbase + t + 1);
    }

    // epilogue: finalize z_{T-1} (hc 0 only; needs all 8 chunks' partials)
    if (hc == 0) {
        wait_peers(bg, hc, tokbase + Tt);
        const int pb = (Tt - 1) & 1;
        float a0 = 0.f, a1 = 0.f, a2 = 0.f, a3 = 0.f;
        const float* base = &g_ff[pb][bg][0][zb * FWD + zl * 4];
        #pragma unroll
        for (int c = 0; c < 8; ++c) {
            float4 v = __ldcg((const float4*)(base + c * (BG * FWD)));
            a0 += v.x; a1 += v.y; a2 += v.z; a3 += v.w;
        }
        int f4 = zl * 4;
        float s = fmaxf(a0 + b1f[f4], 0.f)     * W2f[f4]
                + fmaxf(a1 + b1f[f4 + 1], 0.f) * W2f[f4 + 1]
                + fmaxf(a2 + b1f[f4 + 2], 0.f) * W2f[f4 + 2]
                + fmaxf(a3 + b1f[f4 + 3], 0.f) * W2f[f4 + 3];
        s += __shfl_xor_sync(0xffffffffu, s, 1);
        s += __shfl_xor_sync(0xffffffffu, s, 2);
        s += __shfl_xor_sync(0xffffffffu, s, 4);
        s += __shfl_xor_sync(0xffffffffu, s, 8);
        if (zl == 0) {
            float zn = zloc[zb] + fmaxf(s + *b2s, 0.f);
            out[(bg * BG + zb) * Tt + (Tt - 1)] = zn;
        }
    }
}

extern "C" void kernel_launch(void* const* d_in, const int* in_sizes, int n_in,
                              void* d_out, int out_size) {
    const float* z   = (const float*)d_in[0];
    const float* x   = (const float*)d_in[1];
    const float* h0  = (const float*)d_in[2];
    const float* Wih = (const float*)d_in[3];
    const float* Whh = (const float*)d_in[4];
    const float* b   = (const float*)d_in[5];
    const float* W1  = (const float*)d_in[6];
    const float* b1  = (const float*)d_in[7];
    const float* W2  = (const float*)d_in[8];
    const float* b2  = (const float*)d_in[9];
    float* out = (float*)d_out;

    cudaFuncSetAttribute(lstm_persistent_kernel,
                         cudaFuncAttributeMaxDynamicSharedMemorySize, SMEM_BYTES);
    lstm_persistent_kernel<<<NBLK, THREADS, SMEM_BYTES>>>(
        z, x, h0, Wih, Whh, b, W1, b1, W2, b2, out);
}

// round 7
// speedup vs baseline: 2.6277x; 1.4579x over previous
#include <cuda_runtime.h>

// ---------------------------------------------------------------------------
// Persistent-grid LSTM, crossbar-phase-minimal phase A:
// 128 blocks = 16 batch-groups x 8 hidden-chunks, weights SMEM-resident.
// Phase A: thread tile 8 rows x 4 batches, 4-way k-split, h non-duplicated
// (pair built in-register), row-permuted weight layout for conflict-free
// quarter-warp phases. Dataflow sync via per-block flags (no barriers).
// ---------------------------------------------------------------------------

namespace {
constexpr int Bb   = 256;
constexpr int Tt   = 200;
constexpr int Fd   = 16;
constexpr int Hh   = 256;
constexpr int NBLK = 128;
constexpr int BG   = 16;
constexpr int HCn  = 32;
constexpr int FWD  = 64;
constexpr int THREADS = 256;
constexpr int SLOTS = 280;       // k-slots: 0..16 = [z_t, x], 17..272 = h, pad..279
constexpr int SPQ   = 70;        // slots per k-quarter

// smem offsets (bytes, 16B aligned)
constexpr int OFF_WS   = 0;                  // Ws3: 280*512      = 143360
constexpr int OFF_HST  = 143360;             // hst: 280*80       =  22400
constexpr int OFF_GP   = 165760;             // gpart: 4*16*544   =  34816
constexpr int OFF_W1KT = 200576;             // 32*64 f32         =   8192
constexpr int OFF_CARR = 208768;             // 512 f32           =   2048
constexpr int OFF_HLOC = 210816;             // 512 f32           =   2048
constexpr int OFF_BSL  = 212864;             // 64 float2         =    512
constexpr int OFF_W17  = 213376;             // 128 f32           =    512
constexpr int OFF_B1F  = 213888;             // 64 f32
constexpr int OFF_W2F  = 214144;             // 64 f32
constexpr int OFF_ZLOC = 214400;             // 16 f32 (pad)
constexpr int OFF_B2   = 214464;
constexpr int OFF_TOK  = 214468;
constexpr int SMEM_BYTES = 214528;

constexpr int GP_B  = 544;                   // gpart batch stride (bytes)
constexpr int GP_KQ = 16 * GP_B;             // 8704 per k-quarter

constexpr int OUT_H = Bb * Tt;
constexpr int OUT_C = OUT_H + Bb * Hh;
}

__device__ unsigned g_gflag[16][8][32];
__device__ float    g_hpub[2][16][8][BG * HCn];
__device__ float    g_ff  [2][16][8][BG * FWD];

typedef unsigned long long u64;

__device__ __forceinline__ u64 fma2(u64 a, u64 b, u64 c) {
    u64 d;
    asm("fma.rn.f32x2 %0, %1, %2, %3;" : "=l"(d) : "l"(a), "l"(b), "l"(c));
    return d;
}
__device__ __forceinline__ u64 dup2(float x) {
    u64 d;
    asm("mov.b64 %0, {%1, %1};" : "=l"(d) : "f"(x));
    return d;
}
__device__ __forceinline__ float sigf(float x) {
    return __fdividef(1.0f, 1.0f + __expf(-x));
}
__device__ __forceinline__ float tanh_(float x) {
    return 1.0f - __fdividef(2.0f, __expf(2.0f * x) + 1.0f);
}
__device__ __forceinline__ unsigned ld_acq(const unsigned* p) {
    unsigned v;
    asm volatile("ld.acquire.gpu.global.u32 %0, [%1];" : "=r"(v) : "l"(p) : "memory");
    return v;
}
__device__ __forceinline__ void st_rel(unsigned* p, unsigned v) {
    asm volatile("st.release.gpu.global.u32 [%0], %1;" :: "l"(p), "r"(v) : "memory");
}
__device__ __forceinline__ void wait_peers(int bg, int hc, unsigned need) {
    bool ok = true;
    #pragma unroll
    for (int p = 1; p < 8; ++p)
        ok &= ((int)(ld_acq(&g_gflag[bg][(hc + p) & 7][0]) - need) >= 0);
    if (ok) return;
    for (;;) {
        __nanosleep(32);
        ok = true;
        #pragma unroll
        for (int p = 1; p < 8; ++p)
            ok &= ((int)(ld_acq(&g_gflag[bg][(hc + p) & 7][0]) - need) >= 0);
        if (ok) return;
    }
}

__global__ void __launch_bounds__(THREADS, 1)
lstm_persistent_kernel(const float* __restrict__ zin,  const float* __restrict__ xin,
                       const float* __restrict__ h0,   const float* __restrict__ Wih,
                       const float* __restrict__ Whh,  const float* __restrict__ bias,
                       const float* __restrict__ W1,   const float* __restrict__ b1,
                       const float* __restrict__ W2,   const float* __restrict__ b2,
                       float* __restrict__ out)
{
    extern __shared__ char smem[];
    char*   wsB   = smem + OFF_WS;
    char*   hstB  = smem + OFF_HST;
    char*   gpB   = smem + OFF_GP;
    float*  W1kT  = (float*) (smem + OFF_W1KT);
    float*  carr  = (float*) (smem + OFF_CARR);
    float*  hloc  = (float*) (smem + OFF_HLOC);
    float2* bsl   = (float2*)(smem + OFF_BSL);
    float*  w17s  = (float*) (smem + OFF_W17);
    float*  b1f   = (float*) (smem + OFF_B1F);
    float*  W2f   = (float*) (smem + OFF_W2F);
    float*  zloc  = (float*) (smem + OFF_ZLOC);
    float*  b2s   = (float*) (smem + OFF_B2);
    unsigned* toks= (unsigned*)(smem + OFF_TOK);

    const int tid = threadIdx.x;
    const int bg  = blockIdx.x >> 3;
    const int hc  = blockIdx.x & 7;
    const int k0  = hc * HCn;

    // ---- prologue --------------------------------------------------------
    if (tid == 0) *toks = g_gflag[bg][hc][0];
    // Ws3: slot-major, row-permuted so each thread's 2 LDS.128 are
    // conflict-free 128B quarter phases.  slot s -> k (skip k=17):
    for (int idx = tid; idx < SLOTS * 128; idx += THREADS) {
        int s = idx >> 7, r = idx & 127;
        int p = r >> 1, rl = r & 1, m = p & 3, rr = p >> 2;
        int pos = (m < 2) ? (rr * 4 + m * 2 + rl) : (64 + rr * 4 + (m - 2) * 2 + rl);
        float v = 0.f;
        if (s < 273) {
            int k = (s < 17) ? s : s + 1;
            int grow = ((r >> 5) << 8) + k0 + (r & 31);
            v = (k < 18) ? Wih[grow * 18 + k] : Whh[(grow << 8) + (k - 18)];
        }
        ((float*)(wsB + (size_t)s * 512))[pos] = v;
    }
    for (int idx = tid; idx < SLOTS * 20; idx += THREADS)
        ((float*)hstB)[idx] = 0.f;
    for (int idx = tid; idx < HCn * FWD; idx += THREADS) {
        int j = idx >> 6, f = idx & 63;
        W1kT[idx] = W1[f * Hh + k0 + j];
    }
    if (tid < 128) {
        int r = tid;
        int grow = ((r >> 5) << 8) + k0 + (r & 31);
        w17s[r] = Wih[grow * 18 + 17];
    }
    if (tid < 64) {
        int p = tid;
        int r0i = 2 * p, r1i = r0i + 1;
        float v0 = bias[((r0i >> 5) << 8) + k0 + (r0i & 31)];
        float v1 = bias[((r1i >> 5) << 8) + k0 + (r1i & 31)];
        bsl[p] = make_float2(v0, v1);
        b1f[p] = b1[p];
        W2f[p] = W2[p];
    }
    if (tid == 0) *b2s = b2[0];
    for (int idx = tid; idx < BG * HCn; idx += THREADS) carr[idx] = 0.f;
    if (tid < BG) zloc[tid] = 0.f;
    __syncthreads();
    const unsigned tokbase = *toks;

    // phase-A geometry: kq = k-quarter, 64 threads each: 16 row-octs x 4 batch-quads
    const int kq  = tid >> 6;
    const int g6  = tid & 63;
    const int ro  = g6 & 15;                  // row-oct: pairs 4ro..4ro+3
    const int bq4 = g6 >> 2 >> 2;             // (g6>>4): batch quad 0..3
    const char* wThr = wsB + ro * 16;
    const char* hThr = hstB + bq4 * 16;
    char* gpThr = gpB + kq * GP_KQ + (bq4 * 4) * GP_B + (4 * ro) * 8 + (ro >> 2) * 8;

    // reduce/gate geometry
    const int gb = tid >> 4, jp = tid & 15, j0 = jp * 2;
    // FF geometry
    const int pf = tid & 63, pbq = tid >> 6;
    // fill geometry
    const int fb = tid & 15, fsl = tid >> 4;

    // ---- time loop -------------------------------------------------------
    for (int t = 0; t < Tt; ++t) {
        const int pb = (t - 1) & 1;
        const int cb = t & 1;

        float pa0 = 0.f, pa1 = 0.f, pa2 = 0.f, pa3 = 0.f;
        if (t > 0) {
            wait_peers(bg, hc, tokbase + t);
            // FF partials of step t-1 (8 chunks) -> z_{t-1}
            const float* base = &g_ff[pb][bg][0][gb * FWD + jp * 4];
            #pragma unroll
            for (int c = 0; c < 8; ++c) {
                float4 v = __ldcg((const float4*)(base + c * (BG * FWD)));
                pa0 += v.x; pa1 += v.y; pa2 += v.z; pa3 += v.w;
            }
            // fill peer h chunks into staging (non-dup), coalesced
            #pragma unroll
            for (int p = 1; p < 8; ++p) {
                int c = (hc + p) & 7;
                float2 v = __ldcg((const float2*)&g_hpub[pb][bg][c][tid * 2]);
                int b = tid >> 4, jj = (tid & 15) * 2;
                int s = 17 + 32 * c + jj;
                *(float*)(hstB + (size_t)s * 80 + b * 4)        = v.x;
                *(float*)(hstB + (size_t)(s + 1) * 80 + b * 4)  = v.y;
            }
        } else {
            // t=0: stage h0 for all 256 k-positions
            for (int mloop = 0; mloop < 16; ++mloop) {
                int kk = fsl * 16 + mloop;
                float v = h0[(bg * BG + fb) * Hh + kk];
                *(float*)(hstB + (size_t)(17 + kk) * 80 + fb * 4) = v;
            }
        }

        // S_in: slot 0 = z_t, slots 1..16 = x
        {
            const int bglob = bg * BG + fb;
            const float* xr = xin + (bglob * Tt + t) * Fd;
            float v = (fsl == 0) ? zin[bglob * Tt + t] : xr[fsl - 1];
            *(float*)(hstB + (size_t)fsl * 80 + fb * 4) = v;
            if (fsl == 0)
                *(float*)(hstB + (size_t)16 * 80 + fb * 4) = xr[15];
        }

        // finalize z_{t-1}
        if (t > 0) {
            int f4 = jp * 4;
            float s = fmaxf(pa0 + b1f[f4], 0.f)     * W2f[f4]
                    + fmaxf(pa1 + b1f[f4 + 1], 0.f) * W2f[f4 + 1]
                    + fmaxf(pa2 + b1f[f4 + 2], 0.f) * W2f[f4 + 2]
                    + fmaxf(pa3 + b1f[f4 + 3], 0.f) * W2f[f4 + 3];
            s += __shfl_xor_sync(0xffffffffu, s, 1);
            s += __shfl_xor_sync(0xffffffffu, s, 2);
            s += __shfl_xor_sync(0xffffffffu, s, 4);
            s += __shfl_xor_sync(0xffffffffu, s, 8);
            if (jp == 0) {
                float zn = zloc[gb] + fmaxf(s + *b2s, 0.f);
                zloc[gb] = zn;
                if (hc == 0) out[(bg * BG + gb) * Tt + (t - 1)] = zn;
            }
        }
        __syncthreads();

        // ---- phase A: k-quarter partial GEMV, 8 rows x 4 batches per thread
        {
            u64 a00=0,a01=0,a02=0,a03=0, a10=0,a11=0,a12=0,a13=0;
            u64 a20=0,a21=0,a22=0,a23=0, a30=0,a31=0,a32=0,a33=0;
            const int sbase = kq * SPQ;
            #pragma unroll 5
            for (int ss = 0; ss < SPQ; ++ss) {
                const int s = sbase + ss;
                ulonglong2 W01 = *(const ulonglong2*)(wThr + (size_t)s * 512);
                ulonglong2 W23 = *(const ulonglong2*)(wThr + (size_t)s * 512 + 256);
                float4 hv = *(const float4*)(hThr + (size_t)s * 80);
                u64 h0d = dup2(hv.x), h1d = dup2(hv.y), h2d = dup2(hv.z), h3d = dup2(hv.w);
                a00 = fma2(W01.x, h0d, a00); a10 = fma2(W01.y, h0d, a10);
                a20 = fma2(W23.x, h0d, a20); a30 = fma2(W23.y, h0d, a30);
                a01 = fma2(W01.x, h1d, a01); a11 = fma2(W01.y, h1d, a11);
                a21 = fma2(W23.x, h1d, a21); a31 = fma2(W23.y, h1d, a31);
                a02 = fma2(W01.x, h2d, a02); a12 = fma2(W01.y, h2d, a12);
                a22 = fma2(W23.x, h2d, a22); a32 = fma2(W23.y, h2d, a32);
                a03 = fma2(W01.x, h3d, a03); a13 = fma2(W01.y, h3d, a13);
                a23 = fma2(W23.x, h3d, a23); a33 = fma2(W23.y, h3d, a33);
            }
            // store partials: acc[m][bb] -> gpart[kq][4bq4+bb][pair 4ro+m]
            #pragma unroll
            for (int bb = 0; bb < 4; ++bb) {
                u64* d = (u64*)(gpThr + bb * GP_B);
                u64 v0 = (bb==0)?a00:(bb==1)?a01:(bb==2)?a02:a03;
                u64 v1 = (bb==0)?a10:(bb==1)?a11:(bb==2)?a12:a13;
                u64 v2 = (bb==0)?a20:(bb==1)?a21:(bb==2)?a22:a23;
                u64 v3 = (bb==0)?a30:(bb==1)?a31:(bb==2)?a32:a33;
                d[0] = v0; d[1] = v1; d[2] = v2; d[3] = v3;
            }
        }
        __syncthreads();

        // ---- reduce partials + bias + z*w17; gates; publish h ------------
        {
            float2 G[4];
            #pragma unroll
            for (int g = 0; g < 4; ++g) {
                int pair = g * 16 + jp;
                size_t off = (size_t)gb * GP_B + pair * 8 + (pair >> 4) * 8;
                float2 s0 = *(const float2*)(gpB + off);
                float2 s1 = *(const float2*)(gpB + GP_KQ + off);
                float2 s2 = *(const float2*)(gpB + 2 * GP_KQ + off);
                float2 s3 = *(const float2*)(gpB + 3 * GP_KQ + off);
                float2 bv = bsl[pair];
                G[g].x = s0.x + s1.x + s2.x + s3.x + bv.x;
                G[g].y = s0.y + s1.y + s2.y + s3.y + bv.y;
            }
            float zp = zloc[gb];
            #pragma unroll
            for (int g = 0; g < 4; ++g) {
                G[g].x = fmaf(w17s[g * 32 + j0], zp, G[g].x);
                G[g].y = fmaf(w17s[g * 32 + j0 + 1], zp, G[g].y);
            }
            float2 cc = *(float2*)(carr + gb * 32 + j0);
            float c0 = sigf(G[1].x) * cc.x + sigf(G[0].x) * tanh_(G[2].x);
            float c1 = sigf(G[1].y) * cc.y + sigf(G[0].y) * tanh_(G[2].y);
            float hh0 = sigf(G[3].x) * tanh_(c0);
            float hh1 = sigf(G[3].y) * tanh_(c1);
            *(float2*)(carr + gb * 32 + j0) = make_float2(c0, c1);
            *(float2*)(hloc + gb * 32 + j0) = make_float2(hh0, hh1);
            int s = 17 + k0 + j0;   // own staging slots for next step
            *(float*)(hstB + (size_t)s * 80 + gb * 4)       = hh0;
            *(float*)(hstB + (size_t)(s + 1) * 80 + gb * 4) = hh1;
            *(float2*)&g_hpub[cb][bg][hc][gb * 32 + j0] = make_float2(hh0, hh1);
            if (t == Tt - 1) {
                int bglob = bg * BG + gb;
                *(float2*)&out[OUT_H + bglob * Hh + k0 + j0] = make_float2(hh0, hh1);
                *(float2*)&out[OUT_C + bglob * Hh + k0 + j0] = make_float2(c0, c1);
            }
        }
        __syncthreads();

        // ---- FF k-partials: part[b][f] = sum_j W1[f][k0+j] h[b][j] -------
        {
            float ac0 = 0.f, ac1 = 0.f, ac2 = 0.f, ac3 = 0.f;
            const float4* h4 = (const float4*)hloc;
            #pragma unroll
            for (int jq = 0; jq < 8; ++jq) {
                float4 hq0 = h4[(pbq * 4 + 0) * 8 + jq];
                float4 hq1 = h4[(pbq * 4 + 1) * 8 + jq];
                float4 hq2 = h4[(pbq * 4 + 2) * 8 + jq];
                float4 hq3 = h4[(pbq * 4 + 3) * 8 + jq];
                float w0 = W1kT[(jq * 4 + 0) * 64 + pf];
                float w1 = W1kT[(jq * 4 + 1) * 64 + pf];
                float w2 = W1kT[(jq * 4 + 2) * 64 + pf];
                float w3 = W1kT[(jq * 4 + 3) * 64 + pf];
                ac0 = fmaf(hq0.x, w0, ac0); ac0 = fmaf(hq0.y, w1, ac0);
                ac0 = fmaf(hq0.z, w2, ac0); ac0 = fmaf(hq0.w, w3, ac0);
                ac1 = fmaf(hq1.x, w0, ac1); ac1 = fmaf(hq1.y, w1, ac1);
                ac1 = fmaf(hq1.z, w2, ac1); ac1 = fmaf(hq1.w, w3, ac1);
                ac2 = fmaf(hq2.x, w0, ac2); ac2 = fmaf(hq2.y, w1, ac2);
                ac2 = fmaf(hq2.z, w2, ac2); ac2 = fmaf(hq2.w, w3, ac2);
                ac3 = fmaf(hq3.x, w0, ac3); ac3 = fmaf(hq3.y, w1, ac3);
                ac3 = fmaf(hq3.z, w2, ac3); ac3 = fmaf(hq3.w, w3, ac3);
            }
            float* fp = &g_ff[cb][bg][hc][0];
            fp[(pbq * 4 + 0) * FWD + pf] = ac0;
            fp[(pbq * 4 + 1) * FWD + pf] = ac1;
            fp[(pbq * 4 + 2) * FWD + pf] = ac2;
            fp[(pbq * 4 + 3) * FWD + pf] = ac3;
        }
        __syncthreads();
        if (tid == 0) st_rel(&g_gflag[bg][hc][0], tokbase + t + 1);
    }

    // epilogue: finalize z_{T-1}
    if (hc == 0) {
        wait_peers(bg, hc, tokbase + Tt);
        const int pb = (Tt - 1) & 1;
        float a0 = 0.f, a1 = 0.f, a2 = 0.f, a3 = 0.f;
        const float* base = &g_ff[pb][bg][0][gb * FWD + jp * 4];
        #pragma unroll
        for (int c = 0; c < 8; ++c) {
            float4 v = __ldcg((const float4*)(base + c * (BG * FWD)));
            a0 += v.x; a1 += v.y; a2 += v.z; a3 += v.w;
        }
        int f4 = jp * 4;
        float s = fmaxf(a0 + b1f[f4], 0.f)     * W2f[f4]
                + fmaxf(a1 + b1f[f4 + 1], 0.f) * W2f[f4 + 1]
                + fmaxf(a2 + b1f[f4 + 2], 0.f) * W2f[f4 + 2]
                + fmaxf(a3 + b1f[f4 + 3], 0.f) * W2f[f4 + 3];
        s += __shfl_xor_sync(0xffffffffu, s, 1);
        s += __shfl_xor_sync(0xffffffffu, s, 2);
        s += __shfl_xor_sync(0xffffffffu, s, 4);
        s += __shfl_xor_sync(0xffffffffu, s, 8);
        if (jp == 0) {
            float zn = zloc[gb] + fmaxf(s + *b2s, 0.f);
            out[(bg * BG + gb) * Tt + (Tt - 1)] = zn;
        }
    }
}

extern "C" void kernel_launch(void* const* d_in, const int* in_sizes, int n_in,
                              void* d_out, int out_size) {
    const float* z   = (const float*)d_in[0];
    const float* x   = (const float*)d_in[1];
    const float* h0  = (const float*)d_in[2];
    const float* Wih = (const float*)d_in[3];
    const float* Whh = (const float*)d_in[4];
    const float* b   = (const float*)d_in[5];
    const float* W1  = (const float*)d_in[6];
    const float* b1  = (const float*)d_in[7];
    const float* W2  = (const float*)d_in[8];
    const float* b2  = (const float*)d_in[9];
    float* out = (float*)d_out;

    cudaFuncSetAttribute(lstm_persistent_kernel,
                         cudaFuncAttributeMaxDynamicSharedMemorySize, SMEM_BYTES);
    lstm_persistent_kernel<<<NBLK, THREADS, SMEM_BYTES>>>(
        z, x, h0, Wih, Whh, b, W1, b1, W2, b2, out);
}

// round 8
// speedup vs baseline: 2.7015x; 1.0281x over previous
#include <cuda_runtime.h>

// ---------------------------------------------------------------------------
// Persistent-grid LSTM. Phase A at the crossbar floor: 8 rows x 8 batches per
// thread (16 phases/k), slot-parity warp pairs per k-quarter with a vectorized
// combine pass. MUFU.TANH gates. Dataflow sync via per-block flags.
// ---------------------------------------------------------------------------

namespace {
constexpr int Bb   = 256;
constexpr int Tt   = 200;
constexpr int Fd   = 16;
constexpr int Hh   = 256;
constexpr int NBLK = 128;
constexpr int BG   = 16;
constexpr int HCn  = 32;
constexpr int FWD  = 64;
constexpr int THREADS = 256;
constexpr int SLOTS = 280;       // 0..16 = [z_t, x]; 17..272 = h; pad..279
constexpr int SPQ   = 70;        // slots per k-quarter

constexpr int GP_B  = 576;                   // gpart batch stride (bytes)
constexpr int GP_KQ = 16 * GP_B;             // 9216 per k-quarter

// smem offsets (bytes, 16B aligned)
constexpr int OFF_WS   = 0;                  // Ws3: 280*512      = 143360
constexpr int OFF_HST  = 143360;             // hst: 280*80       =  22400
constexpr int OFF_GP   = 165760;             // gpart: 4*9216     =  36864
constexpr int OFF_W1KT = 202624;             // 32*64 f32         =   8192
constexpr int OFF_CARR = 210816;             // 512 f32           =   2048
constexpr int OFF_HLOC = 212864;             // 512 f32           =   2048
constexpr int OFF_BSL  = 214912;             // 64 float2         =    512
constexpr int OFF_W17  = 215424;             // 128 f32           =    512
constexpr int OFF_B1F  = 215936;             // 64 f32
constexpr int OFF_W2F  = 216192;             // 64 f32
constexpr int OFF_ZLOC = 216448;             // 16 f32 (pad)
constexpr int OFF_B2   = 216512;
constexpr int OFF_TOK  = 216516;
constexpr int SMEM_BYTES = 216576;

constexpr int OUT_H = Bb * Tt;
constexpr int OUT_C = OUT_H + Bb * Hh;
}

__device__ unsigned g_gflag[16][8][32];
__device__ float    g_hpub[2][16][8][BG * HCn];
__device__ float    g_ff  [2][16][8][BG * FWD];

typedef unsigned long long u64;

__device__ __forceinline__ u64 fma2(u64 a, u64 b, u64 c) {
    u64 d;
    asm("fma.rn.f32x2 %0, %1, %2, %3;" : "=l"(d) : "l"(a), "l"(b), "l"(c));
    return d;
}
__device__ __forceinline__ u64 add2(u64 a, u64 b) {
    u64 d;
    asm("add.rn.f32x2 %0, %1, %2;" : "=l"(d) : "l"(a), "l"(b));
    return d;
}
__device__ __forceinline__ u64 dup2(float x) {
    u64 d;
    asm("mov.b64 %0, {%1, %1};" : "=l"(d) : "f"(x));
    return d;
}
__device__ __forceinline__ float tanha(float x) {
    float y;
    asm("tanh.approx.f32 %0, %1;" : "=f"(y) : "f"(x));
    return y;
}
__device__ __forceinline__ float siga(float x) {
    return fmaf(tanha(x * 0.5f), 0.5f, 0.5f);
}
__device__ __forceinline__ unsigned ld_acq(const unsigned* p) {
    unsigned v;
    asm volatile("ld.acquire.gpu.global.u32 %0, [%1];" : "=r"(v) : "l"(p) : "memory");
    return v;
}
__device__ __forceinline__ void st_rel(unsigned* p, unsigned v) {
    asm volatile("st.release.gpu.global.u32 [%0], %1;" :: "l"(p), "r"(v) : "memory");
}
__device__ __forceinline__ void wait_peers(int bg, int hc, unsigned need) {
    bool ok = true;
    #pragma unroll
    for (int p = 1; p < 8; ++p)
        ok &= ((int)(ld_acq(&g_gflag[bg][(hc + p) & 7][0]) - need) >= 0);
    if (ok) return;
    for (;;) {
        __nanosleep(32);
        ok = true;
        #pragma unroll
        for (int p = 1; p < 8; ++p)
            ok &= ((int)(ld_acq(&g_gflag[bg][(hc + p) & 7][0]) - need) >= 0);
        if (ok) return;
    }
}

__global__ void __launch_bounds__(THREADS, 1)
lstm_persistent_kernel(const float* __restrict__ zin,  const float* __restrict__ xin,
                       const float* __restrict__ h0,   const float* __restrict__ Wih,
                       const float* __restrict__ Whh,  const float* __restrict__ bias,
                       const float* __restrict__ W1,   const float* __restrict__ b1,
                       const float* __restrict__ W2,   const float* __restrict__ b2,
                       float* __restrict__ out)
{
    extern __shared__ char smem[];
    char*   wsB   = smem + OFF_WS;
    char*   hstB  = smem + OFF_HST;
    char*   gpB   = smem + OFF_GP;
    float*  W1kT  = (float*) (smem + OFF_W1KT);
    float*  carr  = (float*) (smem + OFF_CARR);
    float*  hloc  = (float*) (smem + OFF_HLOC);
    float2* bsl   = (float2*)(smem + OFF_BSL);
    float*  w17s  = (float*) (smem + OFF_W17);
    float*  b1f   = (float*) (smem + OFF_B1F);
    float*  W2f   = (float*) (smem + OFF_W2F);
    float*  zloc  = (float*) (smem + OFF_ZLOC);
    float*  b2s   = (float*) (smem + OFF_B2);
    unsigned* toks= (unsigned*)(smem + OFF_TOK);

    const int tid = threadIdx.x;
    const int bg  = blockIdx.x >> 3;
    const int hc  = blockIdx.x & 7;
    const int k0  = hc * HCn;

    // ---- prologue --------------------------------------------------------
    if (tid == 0) *toks = g_gflag[bg][hc][0];
    // Ws3: slot-major, row-pair permuted (same layout as r7)
    for (int idx = tid; idx < SLOTS * 128; idx += THREADS) {
        int s = idx >> 7, r = idx & 127;
        int p = r >> 1, rl = r & 1, m = p & 3, rr = p >> 2;
        int pos = (m < 2) ? (rr * 4 + m * 2 + rl) : (64 + rr * 4 + (m - 2) * 2 + rl);
        float v = 0.f;
        if (s < 273) {
            int k = (s < 17) ? s : s + 1;
            int grow = ((r >> 5) << 8) + k0 + (r & 31);
            v = (k < 18) ? Wih[grow * 18 + k] : Whh[(grow << 8) + (k - 18)];
        }
        ((float*)(wsB + (size_t)s * 512))[pos] = v;
    }
    for (int idx = tid; idx < SLOTS * 20; idx += THREADS)
        ((float*)hstB)[idx] = 0.f;
    for (int idx = tid; idx < HCn * FWD; idx += THREADS) {
        int j = idx >> 6, f = idx & 63;
        W1kT[idx] = W1[f * Hh + k0 + j];
    }
    if (tid < 128) {
        int r = tid;
        int grow = ((r >> 5) << 8) + k0 + (r & 31);
        w17s[r] = Wih[grow * 18 + 17];
    }
    if (tid < 64) {
        int p = tid;
        int r0i = 2 * p, r1i = r0i + 1;
        float v0 = bias[((r0i >> 5) << 8) + k0 + (r0i & 31)];
        float v1 = bias[((r1i >> 5) << 8) + k0 + (r1i & 31)];
        bsl[p] = make_float2(v0, v1);
        b1f[p] = b1[p];
        W2f[p] = W2[p];
    }
    if (tid == 0) *b2s = b2[0];
    for (int idx = tid; idx < BG * HCn; idx += THREADS) carr[idx] = 0.f;
    if (tid < BG) zloc[tid] = 0.f;
    __syncthreads();
    const unsigned tokbase = *toks;

    // phase-A geometry: warp pair per k-quarter, slot parity split.
    // thread tile: 8 rows (pairs 4ro..4ro+3) x 8 batches (8bh..8bh+7)
    const int warp = tid >> 5, kq = warp >> 1, wsub = warp & 1;
    const int lan  = tid & 31, ro = lan & 15, bh = lan >> 4;
    const char* wThr = wsB + ro * 16;
    const char* hThr = hstB + bh * 32;
    char* gpThr = gpB + kq * GP_KQ + (bh * 8) * GP_B + ro * 32 + (ro >> 2) * 16;

    // reduce/gate geometry
    const int gb = tid >> 4, jp = tid & 15, j0 = jp * 2;
    // FF geometry
    const int pf = tid & 63, pbq = tid >> 6;
    // fill geometry
    const int fb = tid & 15, fsl = tid >> 4;

    // ---- time loop -------------------------------------------------------
    for (int t = 0; t < Tt; ++t) {
        const int pb = (t - 1) & 1;
        const int cb = t & 1;

        float pa0 = 0.f, pa1 = 0.f, pa2 = 0.f, pa3 = 0.f;
        if (t > 0) {
            wait_peers(bg, hc, tokbase + t);
            const float* base = &g_ff[pb][bg][0][gb * FWD + jp * 4];
            #pragma unroll
            for (int c = 0; c < 8; ++c) {
                float4 v = __ldcg((const float4*)(base + c * (BG * FWD)));
                pa0 += v.x; pa1 += v.y; pa2 += v.z; pa3 += v.w;
            }
            #pragma unroll
            for (int p = 1; p < 8; ++p) {
                int c = (hc + p) & 7;
                float2 v = __ldcg((const float2*)&g_hpub[pb][bg][c][tid * 2]);
                int b = tid >> 4, jj = (tid & 15) * 2;
                int s = 17 + 32 * c + jj;
                *(float*)(hstB + (size_t)s * 80 + b * 4)        = v.x;
                *(float*)(hstB + (size_t)(s + 1) * 80 + b * 4)  = v.y;
            }
        } else {
            for (int mloop = 0; mloop < 16; ++mloop) {
                int kk = fsl * 16 + mloop;
                float v = h0[(bg * BG + fb) * Hh + kk];
                *(float*)(hstB + (size_t)(17 + kk) * 80 + fb * 4) = v;
            }
        }

        // S_in: slot 0 = z_t, slots 1..16 = x
        {
            const int bglob = bg * BG + fb;
            const float* xr = xin + (bglob * Tt + t) * Fd;
            float v = (fsl == 0) ? zin[bglob * Tt + t] : xr[fsl - 1];
            *(float*)(hstB + (size_t)fsl * 80 + fb * 4) = v;
            if (fsl == 0)
                *(float*)(hstB + (size_t)16 * 80 + fb * 4) = xr[15];
        }

        // finalize z_{t-1}
        if (t > 0) {
            int f4 = jp * 4;
            float s = fmaxf(pa0 + b1f[f4], 0.f)     * W2f[f4]
                    + fmaxf(pa1 + b1f[f4 + 1], 0.f) * W2f[f4 + 1]
                    + fmaxf(pa2 + b1f[f4 + 2], 0.f) * W2f[f4 + 2]
                    + fmaxf(pa3 + b1f[f4 + 3], 0.f) * W2f[f4 + 3];
            s += __shfl_xor_sync(0xffffffffu, s, 1);
            s += __shfl_xor_sync(0xffffffffu, s, 2);
            s += __shfl_xor_sync(0xffffffffu, s, 4);
            s += __shfl_xor_sync(0xffffffffu, s, 8);
            if (jp == 0) {
                float zn = zloc[gb] + fmaxf(s + *b2s, 0.f);
                zloc[gb] = zn;
                if (hc == 0) out[(bg * BG + gb) * Tt + (t - 1)] = zn;
            }
        }
        __syncthreads();

        // ---- phase A: 8 rows x 8 batches per thread, parity slots --------
        {
            u64 a[4][8];
            #pragma unroll
            for (int m = 0; m < 4; ++m)
                #pragma unroll
                for (int b = 0; b < 8; ++b) a[m][b] = 0ull;

            const int sbase = kq * SPQ + wsub;
            #pragma unroll 2
            for (int ss = 0; ss < SPQ / 2; ++ss) {
                const int s = sbase + 2 * ss;
                ulonglong2 W01 = *(const ulonglong2*)(wThr + (size_t)s * 512);
                ulonglong2 W23 = *(const ulonglong2*)(wThr + (size_t)s * 512 + 256);
                float4 H0 = *(const float4*)(hThr + (size_t)s * 80);
                float4 H1 = *(const float4*)(hThr + (size_t)s * 80 + 16);
                u64 hd[8];
                hd[0] = dup2(H0.x); hd[1] = dup2(H0.y);
                hd[2] = dup2(H0.z); hd[3] = dup2(H0.w);
                hd[4] = dup2(H1.x); hd[5] = dup2(H1.y);
                hd[6] = dup2(H1.z); hd[7] = dup2(H1.w);
                #pragma unroll
                for (int b = 0; b < 8; ++b) {
                    a[0][b] = fma2(W01.x, hd[b], a[0][b]);
                    a[1][b] = fma2(W01.y, hd[b], a[1][b]);
                    a[2][b] = fma2(W23.x, hd[b], a[2][b]);
                    a[3][b] = fma2(W23.y, hd[b], a[3][b]);
                }
            }
            if (wsub == 0) {
                #pragma unroll
                for (int b = 0; b < 8; ++b) {
                    ulonglong2* d = (ulonglong2*)(gpThr + b * GP_B);
                    d[0] = make_ulonglong2(a[0][b], a[1][b]);
                    d[1] = make_ulonglong2(a[2][b], a[3][b]);
                }
            }
            __syncthreads();
            if (wsub == 1) {
                #pragma unroll
                for (int b = 0; b < 8; ++b) {
                    ulonglong2* d = (ulonglong2*)(gpThr + b * GP_B);
                    ulonglong2 v0 = d[0], v1 = d[1];
                    d[0] = make_ulonglong2(add2(v0.x, a[0][b]), add2(v0.y, a[1][b]));
                    d[1] = make_ulonglong2(add2(v1.x, a[2][b]), add2(v1.y, a[3][b]));
                }
            }
        }
        __syncthreads();

        // ---- reduce partials + bias + z*w17; gates; publish h ------------
        {
            float2 G[4];
            #pragma unroll
            for (int g = 0; g < 4; ++g) {
                int pair = g * 16 + jp;
                size_t off = (size_t)gb * GP_B + pair * 8 + g * 16;
                float2 s0 = *(const float2*)(gpB + off);
                float2 s1 = *(const float2*)(gpB + GP_KQ + off);
                float2 s2 = *(const float2*)(gpB + 2 * GP_KQ + off);
                float2 s3 = *(const float2*)(gpB + 3 * GP_KQ + off);
                float2 bv = bsl[pair];
                G[g].x = s0.x + s1.x + s2.x + s3.x + bv.x;
                G[g].y = s0.y + s1.y + s2.y + s3.y + bv.y;
            }
            float zp = zloc[gb];
            #pragma unroll
            for (int g = 0; g < 4; ++g) {
                G[g].x = fmaf(w17s[g * 32 + j0], zp, G[g].x);
                G[g].y = fmaf(w17s[g * 32 + j0 + 1], zp, G[g].y);
            }
            float2 cc = *(float2*)(carr + gb * 32 + j0);
            float c0 = siga(G[1].x) * cc.x + siga(G[0].x) * tanha(G[2].x);
            float c1 = siga(G[1].y) * cc.y + siga(G[0].y) * tanha(G[2].y);
            float hh0 = siga(G[3].x) * tanha(c0);
            float hh1 = siga(G[3].y) * tanha(c1);
            *(float2*)(carr + gb * 32 + j0) = make_float2(c0, c1);
            *(float2*)(hloc + gb * 32 + j0) = make_float2(hh0, hh1);
            int s = 17 + k0 + j0;   // own staging slots for next step
            *(float*)(hstB + (size_t)s * 80 + gb * 4)       = hh0;
            *(float*)(hstB + (size_t)(s + 1) * 80 + gb * 4) = hh1;
            *(float2*)&g_hpub[cb][bg][hc][gb * 32 + j0] = make_float2(hh0, hh1);
            if (t == Tt - 1) {
                int bglob = bg * BG + gb;
                *(float2*)&out[OUT_H + bglob * Hh + k0 + j0] = make_float2(hh0, hh1);
                *(float2*)&out[OUT_C + bglob * Hh + k0 + j0] = make_float2(c0, c1);
            }
        }
        __syncthreads();

        // ---- FF k-partials: part[b][f] = sum_j W1[f][k0+j] h[b][j] -------
        {
            float ac0 = 0.f, ac1 = 0.f, ac2 = 0.f, ac3 = 0.f;
            const float4* h4 = (const float4*)hloc;
            #pragma unroll
            for (int jq = 0; jq < 8; ++jq) {
                float4 hq0 = h4[(pbq * 4 + 0) * 8 + jq];
                float4 hq1 = h4[(pbq * 4 + 1) * 8 + jq];
                float4 hq2 = h4[(pbq * 4 + 2) * 8 + jq];
                float4 hq3 = h4[(pbq * 4 + 3) * 8 + jq];
                float w0 = W1kT[(jq * 4 + 0) * 64 + pf];
                float w1 = W1kT[(jq * 4 + 1) * 64 + pf];
                float w2 = W1kT[(jq * 4 + 2) * 64 + pf];
                float w3 = W1kT[(jq * 4 + 3) * 64 + pf];
                ac0 = fmaf(hq0.x, w0, ac0); ac0 = fmaf(hq0.y, w1, ac0);
                ac0 = fmaf(hq0.z, w2, ac0); ac0 = fmaf(hq0.w, w3, ac0);
                ac1 = fmaf(hq1.x, w0, ac1); ac1 = fmaf(hq1.y, w1, ac1);
                ac1 = fmaf(hq1.z, w2, ac1); ac1 = fmaf(hq1.w, w3, ac1);
                ac2 = fmaf(hq2.x, w0, ac2); ac2 = fmaf(hq2.y, w1, ac2);
                ac2 = fmaf(hq2.z, w2, ac2); ac2 = fmaf(hq2.w, w3, ac2);
                ac3 = fmaf(hq3.x, w0, ac3); ac3 = fmaf(hq3.y, w1, ac3);
                ac3 = fmaf(hq3.z, w2, ac3); ac3 = fmaf(hq3.w, w3, ac3);
            }
            float* fp = &g_ff[cb][bg][hc][0];
            fp[(pbq * 4 + 0) * FWD + pf] = ac0;
            fp[(pbq * 4 + 1) * FWD + pf] = ac1;
            fp[(pbq * 4 + 2) * FWD + pf] = ac2;
            fp[(pbq * 4 + 3) * FWD + pf] = ac3;
        }
        __syncthreads();
        if (tid == 0) st_rel(&g_gflag[bg][hc][0], tokbase + t + 1);
    }

    // epilogue: finalize z_{T-1}
    if (hc == 0) {
        wait_peers(bg, hc, tokbase + Tt);
        const int pb = (Tt - 1) & 1;
        float a0 = 0.f, a1 = 0.f, a2 = 0.f, a3 = 0.f;
        const float* base = &g_ff[pb][bg][0][gb * FWD + jp * 4];
        #pragma unroll
        for (int c = 0; c < 8; ++c) {
            float4 v = __ldcg((const float4*)(base + c * (BG * FWD)));
            a0 += v.x; a1 += v.y; a2 += v.z; a3 += v.w;
        }
        int f4 = jp * 4;
        float s = fmaxf(a0 + b1f[f4], 0.f)     * W2f[f4]
                + fmaxf(a1 + b1f[f4 + 1], 0.f) * W2f[f4 + 1]
                + fmaxf(a2 + b1f[f4 + 2], 0.f) * W2f[f4 + 2]
                + fmaxf(a3 + b1f[f4 + 3], 0.f) * W2f[f4 + 3];
        s += __shfl_xor_sync(0xffffffffu, s, 1);
        s += __shfl_xor_sync(0xffffffffu, s, 2);
        s += __shfl_xor_sync(0xffffffffu, s, 4);
        s += __shfl_xor_sync(0xffffffffu, s, 8);
        if (jp == 0) {
            float zn = zloc[gb] + fmaxf(s + *b2s, 0.f);
            out[(bg * BG + gb) * Tt + (Tt - 1)] = zn;
        }
    }
}

extern "C" void kernel_launch(void* const* d_in, const int* in_sizes, int n_in,
                              void* d_out, int out_size) {
    const float* z   = (const float*)d_in[0];
    const float* x   = (const float*)d_in[1];
    const float* h0  = (const float*)d_in[2];
    const float* Wih = (const float*)d_in[3];
    const float* Whh = (const float*)d_in[4];
    const float* b   = (const float*)d_in[5];
    const float* W1  = (const float*)d_in[6];
    const float* b1  = (const float*)d_in[7];
    const float* W2  = (const float*)d_in[8];
    const float* b2  = (const float*)d_in[9];
    float* out = (float*)d_out;

    cudaFuncSetAttribute(lstm_persistent_kernel,
                         cudaFuncAttributeMaxDynamicSharedMemorySize, SMEM_BYTES);
    lstm_persistent_kernel<<<NBLK, THREADS, SMEM_BYTES>>>(
        z, x, h0, Wih, Whh, b, W1, b1, W2, b2, out);
}